// round 1
// baseline (speedup 1.0000x reference)
#include <cuda_runtime.h>

// ---------------------------------------------------------------------------
// L2Attention: out = (softmax(-L2dist(q,q)^2 * d^-0.5) @ v) @ Wo^T + bo
//   q = x @ Wq^T + bq,  v = x @ Wv^T + bv
// b=4, n=1024, dim=1024, heads=16, d=64
// ---------------------------------------------------------------------------

#define M_ROWS 4096   // b * n
#define DIM    1024
#define NHEAD  16
#define DHEAD  64

// scratch (allocation-free rule: use __device__ globals)
__device__ float g_q[M_ROWS * DIM];
__device__ float g_v[M_ROWS * DIM];
__device__ float g_a[M_ROWS * DIM];

// ---------------------------------------------------------------------------
// GEMM: C[M,N] = A[M,K] @ B[N,K]^T + bias[N]   (torch Linear form)
// block tile 128(M) x 64(N), K-step 16, 256 threads, 8x4 per-thread microtile
// ---------------------------------------------------------------------------
__global__ __launch_bounds__(256) void gemm_bias_kernel(
    const float* __restrict__ A, const float* __restrict__ B,
    const float* __restrict__ bias, float* __restrict__ C,
    int M, int N, int K)
{
    __shared__ float As[128 * 17];
    __shared__ float Bs[64 * 17];

    const int t  = threadIdx.x;
    const int tx = t & 15;        // 0..15 -> N
    const int ty = t >> 4;        // 0..15 -> M
    const int i0 = blockIdx.y * 128;
    const int j0 = blockIdx.x * 64;

    float acc[8][4];
#pragma unroll
    for (int ii = 0; ii < 8; ii++)
#pragma unroll
        for (int jj = 0; jj < 4; jj++) acc[ii][jj] = 0.f;

    for (int k0 = 0; k0 < K; k0 += 16) {
        // load A tile 128x16 (8 elems/thread), coalesced rows of 16
#pragma unroll
        for (int l = 0; l < 8; l++) {
            int idx = t + l * 256;
            int r = idx >> 4, c = idx & 15;
            As[r * 17 + c] = A[(size_t)(i0 + r) * K + k0 + c];
        }
        // load B tile 64x16 (4 elems/thread)
#pragma unroll
        for (int l = 0; l < 4; l++) {
            int idx = t + l * 256;
            int r = idx >> 4, c = idx & 15;
            Bs[r * 17 + c] = B[(size_t)(j0 + r) * K + k0 + c];
        }
        __syncthreads();

#pragma unroll
        for (int k = 0; k < 16; k++) {
            float av[8], bv[4];
#pragma unroll
            for (int ii = 0; ii < 8; ii++) av[ii] = As[(ty + 16 * ii) * 17 + k];
#pragma unroll
            for (int jj = 0; jj < 4; jj++) bv[jj] = Bs[(tx + 16 * jj) * 17 + k];
#pragma unroll
            for (int ii = 0; ii < 8; ii++)
#pragma unroll
                for (int jj = 0; jj < 4; jj++)
                    acc[ii][jj] = fmaf(av[ii], bv[jj], acc[ii][jj]);
        }
        __syncthreads();
    }

#pragma unroll
    for (int jj = 0; jj < 4; jj++) {
        float bb = bias[j0 + tx + 16 * jj];
#pragma unroll
        for (int ii = 0; ii < 8; ii++) {
            C[(size_t)(i0 + ty + 16 * ii) * N + (j0 + tx + 16 * jj)] =
                acc[ii][jj] + bb;
        }
    }
}

// ---------------------------------------------------------------------------
// Fused attention per (b,h): 128-query block streams over 128-key tiles.
// scores = (2*q_i.q_j - |q_i|^2 - |q_j|^2) * 0.125  (<= ~0, diag = 0)
//   -> softmax needs NO max subtraction: exp(score) in (0,1], denom >= 1.
// q,v layout: [b*n, dim] row-major; head h occupies cols [h*64, h*64+64).
// output layout: [b, n, h*d] row-major (ready for the O-projection GEMM).
// ---------------------------------------------------------------------------
#define ATTN_SMEM_FLOATS (128*65 + 128*65 + 128*64 + 128*129 + 128 + 128)

__global__ __launch_bounds__(256) void attn_kernel(
    const float* __restrict__ q, const float* __restrict__ v,
    float* __restrict__ o)
{
    extern __shared__ float sm[];
    float* Qs  = sm;                  // [128][65]
    float* Ks  = Qs + 128 * 65;      // [128][65]
    float* Vs  = Ks + 128 * 65;      // [128][64]
    float* S   = Vs + 128 * 64;      // [128][129]  exp(scores)
    float* sqi = S + 128 * 129;      // [128]
    float* sqj = sqi + 128;          // [128]

    const int bh = blockIdx.y;
    const int b  = bh >> 4;
    const int h  = bh & 15;
    const int qt = blockIdx.x * 128;
    const int t  = threadIdx.x;

    const float* qbase = q + (size_t)b * 1024 * DIM + h * DHEAD;
    const float* vbase = v + (size_t)b * 1024 * DIM + h * DHEAD;

    // ---- load Q tile (128 rows x 64 floats) ----
#pragma unroll
    for (int l = 0; l < 8; l++) {
        int idx = t + l * 256;                // 0..2047 (float4 units)
        int r = idx >> 4, c4 = (idx & 15) * 4;
        float4 val = *(const float4*)(qbase + (size_t)(qt + r) * DIM + c4);
        Qs[r * 65 + c4 + 0] = val.x;
        Qs[r * 65 + c4 + 1] = val.y;
        Qs[r * 65 + c4 + 2] = val.z;
        Qs[r * 65 + c4 + 3] = val.w;
    }
    __syncthreads();
    if (t < 128) {
        float s = 0.f;
#pragma unroll
        for (int k = 0; k < 64; k++) { float xx = Qs[t * 65 + k]; s = fmaf(xx, xx, s); }
        sqi[t] = s;
    }

    float acc[32];
#pragma unroll
    for (int d = 0; d < 32; d++) acc[d] = 0.f;
    float denom = 0.f;

    const int r_own = t >> 1;            // owned query row (0..127)
    const int ch    = (t & 1) * 32;      // owned half of head dim
    const int tx = t & 15, ty = t >> 4;  // score microtile coords
    const float scale = 0.125f;          // d^-0.5, d=64

    for (int kt = 0; kt < 1024; kt += 128) {
        __syncthreads();   // previous tile's S/Vs fully consumed

        // ---- load K (=q rows) and V tiles ----
#pragma unroll
        for (int l = 0; l < 8; l++) {
            int idx = t + l * 256;
            int r = idx >> 4, c4 = (idx & 15) * 4;
            float4 kv = *(const float4*)(qbase + (size_t)(kt + r) * DIM + c4);
            Ks[r * 65 + c4 + 0] = kv.x;
            Ks[r * 65 + c4 + 1] = kv.y;
            Ks[r * 65 + c4 + 2] = kv.z;
            Ks[r * 65 + c4 + 3] = kv.w;
            float4 vv = *(const float4*)(vbase + (size_t)(kt + r) * DIM + c4);
            *(float4*)(&Vs[r * 64 + c4]) = vv;
        }
        __syncthreads();
        if (t < 128) {
            float s = 0.f;
#pragma unroll
            for (int k = 0; k < 64; k++) { float xx = Ks[t * 65 + k]; s = fmaf(xx, xx, s); }
            sqj[t] = s;
        }
        __syncthreads();

        // ---- scores: 8x8 per-thread microtile of the 128x128 score tile ----
        float cs[8][8];
#pragma unroll
        for (int ii = 0; ii < 8; ii++)
#pragma unroll
            for (int jj = 0; jj < 8; jj++) cs[ii][jj] = 0.f;

#pragma unroll
        for (int k = 0; k < 64; k++) {
            float aq[8], bk[8];
#pragma unroll
            for (int ii = 0; ii < 8; ii++) aq[ii] = Qs[(ty + 16 * ii) * 65 + k];
#pragma unroll
            for (int jj = 0; jj < 8; jj++) bk[jj] = Ks[(tx + 16 * jj) * 65 + k];
#pragma unroll
            for (int ii = 0; ii < 8; ii++)
#pragma unroll
                for (int jj = 0; jj < 8; jj++)
                    cs[ii][jj] = fmaf(aq[ii], bk[jj], cs[ii][jj]);
        }

#pragma unroll
        for (int ii = 0; ii < 8; ii++) {
            int i = ty + 16 * ii;
            float si = sqi[i];
#pragma unroll
            for (int jj = 0; jj < 8; jj++) {
                int j = tx + 16 * jj;
                float s = (2.f * cs[ii][jj] - si - sqj[j]) * scale;
                S[i * 129 + j] = __expf(s);
            }
        }
        __syncthreads();

        // ---- PV accumulate: each thread owns (row r_own, 32 of 64 dims) ----
#pragma unroll 4
        for (int j = 0; j < 128; j++) {
            float p = S[r_own * 129 + j];
            denom += p;
            const float4* vr = (const float4*)(&Vs[j * 64 + ch]);
#pragma unroll
            for (int d4 = 0; d4 < 8; d4++) {
                float4 vv = vr[d4];
                acc[d4 * 4 + 0] = fmaf(p, vv.x, acc[d4 * 4 + 0]);
                acc[d4 * 4 + 1] = fmaf(p, vv.y, acc[d4 * 4 + 1]);
                acc[d4 * 4 + 2] = fmaf(p, vv.z, acc[d4 * 4 + 2]);
                acc[d4 * 4 + 3] = fmaf(p, vv.w, acc[d4 * 4 + 3]);
            }
        }
    }

    // ---- normalize + write [b, n, h*64 + d] ----
    float inv = 1.f / denom;
    float* orow = o + (size_t)(b * 1024 + qt + r_own) * DIM + h * DHEAD + ch;
#pragma unroll
    for (int d4 = 0; d4 < 8; d4++) {
        float4 w;
        w.x = acc[d4 * 4 + 0] * inv;
        w.y = acc[d4 * 4 + 1] * inv;
        w.z = acc[d4 * 4 + 2] * inv;
        w.w = acc[d4 * 4 + 3] * inv;
        *(float4*)(orow + d4 * 4) = w;
    }
}

// ---------------------------------------------------------------------------
extern "C" void kernel_launch(void* const* d_in, const int* in_sizes, int n_in,
                              void* d_out, int out_size)
{
    const float* x  = (const float*)d_in[0];
    const float* Wq = (const float*)d_in[1];
    const float* bq = (const float*)d_in[2];
    const float* Wv = (const float*)d_in[3];
    const float* bv = (const float*)d_in[4];
    const float* Wo = (const float*)d_in[5];
    const float* bo = (const float*)d_in[6];
    float* out = (float*)d_out;

    float *qp, *vp, *ap;
    cudaGetSymbolAddress((void**)&qp, g_q);
    cudaGetSymbolAddress((void**)&vp, g_v);
    cudaGetSymbolAddress((void**)&ap, g_a);

    const size_t smem = ATTN_SMEM_FLOATS * sizeof(float);   // ~166 KB
    cudaFuncSetAttribute(attn_kernel,
                         cudaFuncAttributeMaxDynamicSharedMemorySize,
                         (int)smem);

    dim3 ggrid(DIM / 64, M_ROWS / 128);   // (16, 32)
    gemm_bias_kernel<<<ggrid, 256>>>(x, Wq, bq, qp, M_ROWS, DIM, DIM);
    gemm_bias_kernel<<<ggrid, 256>>>(x, Wv, bv, vp, M_ROWS, DIM, DIM);
    attn_kernel<<<dim3(8, 64), 256, smem>>>(qp, vp, ap);
    gemm_bias_kernel<<<ggrid, 256>>>(ap, Wo, bo, out, M_ROWS, DIM, DIM);
}

// round 2
// speedup vs baseline: 3.9719x; 3.9719x over previous
#include <cuda_runtime.h>
#include <cstdint>

// ---------------------------------------------------------------------------
// L2Attention via tf32 mma.sync (m16n8k8) on the tensor pipe.
// b=4, n=1024, dim=1024, heads=16, d=64
// ---------------------------------------------------------------------------

#define M_ROWS 4096   // b * n
#define DIM    1024
#define NHEAD  16
#define DHEAD  64

// scratch (allocation-free rule: use __device__ globals)
__device__ float g_q[M_ROWS * DIM];
__device__ float g_v[M_ROWS * DIM];
__device__ float g_a[M_ROWS * DIM];

// tf32 round (keeps fp32 format, low 13 mantissa bits zeroed)
__device__ __forceinline__ float tf32r(float x) {
    uint32_t u;
    asm("cvt.rna.tf32.f32 %0, %1;" : "=r"(u) : "f"(x));
    return __uint_as_float(u);
}

// D += A(16x8,row) * B(8x8,col) ; tf32 inputs (as b32 regs), f32 accum
__device__ __forceinline__ void mma_tf32(float c[4],
                                         uint32_t a0, uint32_t a1,
                                         uint32_t a2, uint32_t a3,
                                         uint32_t b0, uint32_t b1) {
    asm volatile(
        "mma.sync.aligned.m16n8k8.row.col.f32.tf32.tf32.f32 "
        "{%0,%1,%2,%3}, {%4,%5,%6,%7}, {%8,%9}, {%0,%1,%2,%3};\n"
        : "+f"(c[0]), "+f"(c[1]), "+f"(c[2]), "+f"(c[3])
        : "r"(a0), "r"(a1), "r"(a2), "r"(a3), "r"(b0), "r"(b1));
}

// ---------------------------------------------------------------------------
// GEMM: C[M,N] = A[M,K] @ B[N,K]^T + bias[N]    (torch Linear)
// CTA tile 128x128, 8 warps, each warp 64(M)x32(N), K-step 32.
// ---------------------------------------------------------------------------
#define GS 36   // smem row stride: (4g+t)%32 conflict-free fragment loads

__global__ __launch_bounds__(256) void gemm_tf32_kernel(
    const float* __restrict__ A, const float* __restrict__ B,
    const float* __restrict__ bias, float* __restrict__ C,
    int M, int N, int K)
{
    __shared__ float As[128 * GS];
    __shared__ float Bs[128 * GS];

    const int t    = threadIdx.x;
    const int w    = t >> 5;
    const int lane = t & 31;
    const int g    = lane >> 2;   // groupID
    const int tq   = lane & 3;    // threadID in group
    const int wm   = w >> 2;      // 0..1
    const int wn   = w & 3;       // 0..3
    const int bm   = blockIdx.y * 128;
    const int bn   = blockIdx.x * 128;

    float acc[4][4][4];
#pragma unroll
    for (int i = 0; i < 4; i++)
#pragma unroll
        for (int j = 0; j < 4; j++)
#pragma unroll
            for (int r = 0; r < 4; r++) acc[i][j][r] = 0.f;

    for (int k0 = 0; k0 < K; k0 += 32) {
        // stage tiles (128 x 32), tf32-converted, float4 global loads
#pragma unroll
        for (int l = 0; l < 4; l++) {
            int idx = t + l * 256;           // 0..1023 float4 units
            int r = idx >> 3, c4 = (idx & 7) * 4;
            float4 va = *(const float4*)(A + (size_t)(bm + r) * K + k0 + c4);
            float* da = As + r * GS + c4;
            da[0] = tf32r(va.x); da[1] = tf32r(va.y);
            da[2] = tf32r(va.z); da[3] = tf32r(va.w);
            float4 vb = *(const float4*)(B + (size_t)(bn + r) * K + k0 + c4);
            float* db = Bs + r * GS + c4;
            db[0] = tf32r(vb.x); db[1] = tf32r(vb.y);
            db[2] = tf32r(vb.z); db[3] = tf32r(vb.w);
        }
        __syncthreads();

#pragma unroll
        for (int ks = 0; ks < 4; ks++) {
            const int kk = ks * 8;
            uint32_t a[4][4], b[4][2];
#pragma unroll
            for (int i = 0; i < 4; i++) {
                const float* ar = As + (wm * 64 + i * 16 + g) * GS + kk + tq;
                a[i][0] = __float_as_uint(ar[0]);
                a[i][1] = __float_as_uint(ar[8 * GS]);
                a[i][2] = __float_as_uint(ar[4]);
                a[i][3] = __float_as_uint(ar[8 * GS + 4]);
            }
#pragma unroll
            for (int j = 0; j < 4; j++) {
                const float* br = Bs + (wn * 32 + j * 8 + g) * GS + kk + tq;
                b[j][0] = __float_as_uint(br[0]);
                b[j][1] = __float_as_uint(br[4]);
            }
#pragma unroll
            for (int i = 0; i < 4; i++)
#pragma unroll
                for (int j = 0; j < 4; j++)
                    mma_tf32(acc[i][j], a[i][0], a[i][1], a[i][2], a[i][3],
                             b[j][0], b[j][1]);
        }
        __syncthreads();
    }

    // epilogue: bias + store
#pragma unroll
    for (int i = 0; i < 4; i++) {
        int row0 = bm + wm * 64 + i * 16 + g;
#pragma unroll
        for (int j = 0; j < 4; j++) {
            int col0 = bn + wn * 32 + j * 8 + 2 * tq;
            float b0 = bias[col0], b1 = bias[col0 + 1];
            C[(size_t)row0 * N + col0]           = acc[i][j][0] + b0;
            C[(size_t)row0 * N + col0 + 1]       = acc[i][j][1] + b1;
            C[(size_t)(row0 + 8) * N + col0]     = acc[i][j][2] + b0;
            C[(size_t)(row0 + 8) * N + col0 + 1] = acc[i][j][3] + b1;
        }
    }
}

// ---------------------------------------------------------------------------
// Fused attention, tf32 tensor-core scores (QK^T) and PV.
// scores = (2*q_i.q_j - |q_i|^2 - |q_j|^2) * 0.125  (<= ~0) -> no max needed.
// Each warp owns 16 query rows; O accumulated in C-fragments across key tiles.
// ---------------------------------------------------------------------------
#define QS 68    // Q/K stride: (4g+t)%32 conflict-free
#define VS 72    // V stride:   (8t+g)%32 conflict-free
#define SS 132   // S stride:   (4g+t)%32 conflict-free
#define ATTN_SMEM_FLOATS (128*QS + 128*QS + 128*VS + 128*SS + 256)

__global__ __launch_bounds__(256) void attn_tf32_kernel(
    const float* __restrict__ q, const float* __restrict__ v,
    float* __restrict__ o)
{
    extern __shared__ float sm[];
    float* Qs  = sm;
    float* Ks  = Qs + 128 * QS;
    float* Vs  = Ks + 128 * QS;
    float* Ss  = Vs + 128 * VS;
    float* sqi = Ss + 128 * SS;
    float* sqj = sqi + 128;

    const int bh = blockIdx.y;
    const int b  = bh >> 4;
    const int h  = bh & 15;
    const int qt = blockIdx.x * 128;
    const int t  = threadIdx.x;
    const int w    = t >> 5;
    const int lane = t & 31;
    const int g    = lane >> 2;
    const int tq   = lane & 3;
    const int i0   = 16 * w;      // warp's query-row base within tile

    const float* qbase = q + (size_t)b * 1024 * DIM + h * DHEAD;
    const float* vbase = v + (size_t)b * 1024 * DIM + h * DHEAD;

    // ---- load Q tile (128 x 64), tf32-converted ----
#pragma unroll
    for (int l = 0; l < 8; l++) {
        int idx = t + l * 256;                 // float4 units
        int r = idx >> 4, c4 = (idx & 15) * 4;
        float4 va = *(const float4*)(qbase + (size_t)(qt + r) * DIM + c4);
        float* d = Qs + r * QS + c4;
        d[0] = tf32r(va.x); d[1] = tf32r(va.y);
        d[2] = tf32r(va.z); d[3] = tf32r(va.w);
    }
    __syncthreads();
    if (t < 128) {
        float s = 0.f;
#pragma unroll
        for (int k = 0; k < 64; k++) { float xx = Qs[t * QS + k]; s = fmaf(xx, xx, s); }
        sqi[t] = s;
    }

    float oacc[8][4];
#pragma unroll
    for (int j = 0; j < 8; j++)
#pragma unroll
        for (int r = 0; r < 4; r++) oacc[j][r] = 0.f;
    float den_lo = 0.f, den_hi = 0.f;
    const float scale = 0.125f;

    for (int kt = 0; kt < 1024; kt += 128) {
        __syncthreads();   // previous iter's Ss/Vs fully consumed

        // ---- load K and V tiles (tf32-converted) ----
#pragma unroll
        for (int l = 0; l < 8; l++) {
            int idx = t + l * 256;
            int r = idx >> 4, c4 = (idx & 15) * 4;
            float4 kv = *(const float4*)(qbase + (size_t)(kt + r) * DIM + c4);
            float* dk = Ks + r * QS + c4;
            dk[0] = tf32r(kv.x); dk[1] = tf32r(kv.y);
            dk[2] = tf32r(kv.z); dk[3] = tf32r(kv.w);
            float4 vv = *(const float4*)(vbase + (size_t)(kt + r) * DIM + c4);
            float* dv = Vs + r * VS + c4;
            dv[0] = tf32r(vv.x); dv[1] = tf32r(vv.y);
            dv[2] = tf32r(vv.z); dv[3] = tf32r(vv.w);
        }
        __syncthreads();
        if (t < 128) {
            float s = 0.f;
#pragma unroll
            for (int k = 0; k < 64; k++) { float xx = Ks[t * QS + k]; s = fmaf(xx, xx, s); }
            sqj[t] = s;
        }
        __syncthreads();

        const float si_lo = sqi[i0 + g];
        const float si_hi = sqi[i0 + 8 + g];

        // ---- scores: 16 rows x 128 cols per warp, 4 nsubs per chunk ----
#pragma unroll
        for (int jc = 0; jc < 4; jc++) {
            float c[4][4];
#pragma unroll
            for (int jj = 0; jj < 4; jj++)
#pragma unroll
                for (int r = 0; r < 4; r++) c[jj][r] = 0.f;

#pragma unroll
            for (int ks = 0; ks < 8; ks++) {
                const float* qr = Qs + (i0 + g) * QS + ks * 8 + tq;
                uint32_t a0 = __float_as_uint(qr[0]);
                uint32_t a1 = __float_as_uint(qr[8 * QS]);
                uint32_t a2 = __float_as_uint(qr[4]);
                uint32_t a3 = __float_as_uint(qr[8 * QS + 4]);
#pragma unroll
                for (int jj = 0; jj < 4; jj++) {
                    const float* kr = Ks + ((jc * 4 + jj) * 8 + g) * QS + ks * 8 + tq;
                    uint32_t b0 = __float_as_uint(kr[0]);
                    uint32_t b1 = __float_as_uint(kr[4]);
                    mma_tf32(c[jj], a0, a1, a2, a3, b0, b1);
                }
            }
            // exp + tf32 round + store + denom accumulate
#pragma unroll
            for (int jj = 0; jj < 4; jj++) {
                int cb = (jc * 4 + jj) * 8 + 2 * tq;
                float sj0 = sqj[cb], sj1 = sqj[cb + 1];
                float e00 = tf32r(__expf((2.f * c[jj][0] - si_lo - sj0) * scale));
                float e01 = tf32r(__expf((2.f * c[jj][1] - si_lo - sj1) * scale));
                float e10 = tf32r(__expf((2.f * c[jj][2] - si_hi - sj0) * scale));
                float e11 = tf32r(__expf((2.f * c[jj][3] - si_hi - sj1) * scale));
                den_lo += e00 + e01;
                den_hi += e10 + e11;
                float* s_lo = Ss + (i0 + g) * SS + cb;
                float* s_hi = Ss + (i0 + 8 + g) * SS + cb;
                s_lo[0] = e00; s_lo[1] = e01;
                s_hi[0] = e10; s_hi[1] = e11;
            }
        }
        __syncthreads();

        // ---- PV: O(16x64 per warp) += P(16x128) @ V(128x64) ----
#pragma unroll
        for (int ks = 0; ks < 16; ks++) {
            const float* sr = Ss + (i0 + g) * SS + ks * 8 + tq;
            uint32_t a0 = __float_as_uint(sr[0]);
            uint32_t a1 = __float_as_uint(sr[8 * SS]);
            uint32_t a2 = __float_as_uint(sr[4]);
            uint32_t a3 = __float_as_uint(sr[8 * SS + 4]);
#pragma unroll
            for (int j = 0; j < 8; j++) {
                uint32_t b0 = __float_as_uint(Vs[(ks * 8 + tq) * VS + j * 8 + g]);
                uint32_t b1 = __float_as_uint(Vs[(ks * 8 + tq + 4) * VS + j * 8 + g]);
                mma_tf32(oacc[j], a0, a1, a2, a3, b0, b1);
            }
        }
    }

    // ---- reduce denominators within each quad (lanes sharing a row) ----
    den_lo += __shfl_xor_sync(0xffffffffu, den_lo, 1);
    den_lo += __shfl_xor_sync(0xffffffffu, den_lo, 2);
    den_hi += __shfl_xor_sync(0xffffffffu, den_hi, 1);
    den_hi += __shfl_xor_sync(0xffffffffu, den_hi, 2);
    const float inv_lo = 1.f / den_lo;
    const float inv_hi = 1.f / den_hi;

    // ---- write O: [b, n, h*64 + d] ----
    float* orow_lo = o + (size_t)(b * 1024 + qt + i0 + g) * DIM + h * DHEAD;
    float* orow_hi = o + (size_t)(b * 1024 + qt + i0 + 8 + g) * DIM + h * DHEAD;
#pragma unroll
    for (int j = 0; j < 8; j++) {
        int col = j * 8 + 2 * tq;
        orow_lo[col]     = oacc[j][0] * inv_lo;
        orow_lo[col + 1] = oacc[j][1] * inv_lo;
        orow_hi[col]     = oacc[j][2] * inv_hi;
        orow_hi[col + 1] = oacc[j][3] * inv_hi;
    }
}

// ---------------------------------------------------------------------------
extern "C" void kernel_launch(void* const* d_in, const int* in_sizes, int n_in,
                              void* d_out, int out_size)
{
    const float* x  = (const float*)d_in[0];
    const float* Wq = (const float*)d_in[1];
    const float* bq = (const float*)d_in[2];
    const float* Wv = (const float*)d_in[3];
    const float* bv = (const float*)d_in[4];
    const float* Wo = (const float*)d_in[5];
    const float* bo = (const float*)d_in[6];
    float* out = (float*)d_out;

    float *qp, *vp, *ap;
    cudaGetSymbolAddress((void**)&qp, g_q);
    cudaGetSymbolAddress((void**)&vp, g_v);
    cudaGetSymbolAddress((void**)&ap, g_a);

    const size_t smem = ATTN_SMEM_FLOATS * sizeof(float);   // ~172 KB
    cudaFuncSetAttribute(attn_tf32_kernel,
                         cudaFuncAttributeMaxDynamicSharedMemorySize,
                         (int)smem);

    dim3 ggrid(DIM / 128, M_ROWS / 128);   // (8, 32)
    gemm_tf32_kernel<<<ggrid, 256>>>(x, Wq, bq, qp, M_ROWS, DIM, DIM);
    gemm_tf32_kernel<<<ggrid, 256>>>(x, Wv, bv, vp, M_ROWS, DIM, DIM);
    attn_tf32_kernel<<<dim3(8, 64), 256, smem>>>(qp, vp, ap);
    gemm_tf32_kernel<<<ggrid, 256>>>(ap, Wo, bo, out, M_ROWS, DIM, DIM);
}

// round 3
// speedup vs baseline: 4.7176x; 1.1878x over previous
#include <cuda_runtime.h>
#include <cstdint>

// ---------------------------------------------------------------------------
// L2Attention via tf32 mma.sync, double-buffered cp.async pipelines.
// b=4, n=1024, dim=1024, heads=16, d=64
// ---------------------------------------------------------------------------

#define M_ROWS 4096
#define DIM    1024

// scratch (__device__ globals: allocation-free rule)
__device__ float g_q[M_ROWS * DIM];
__device__ float g_v[M_ROWS * DIM];
__device__ float g_a[M_ROWS * DIM];
__device__ float g_x[M_ROWS * DIM];
__device__ float g_wq[DIM * DIM];
__device__ float g_wv[DIM * DIM];
__device__ float g_wo[DIM * DIM];

__device__ __forceinline__ float tf32r(float x) {
    uint32_t u;
    asm("cvt.rna.tf32.f32 %0, %1;" : "=r"(u) : "f"(x));
    return __uint_as_float(u);
}

__device__ __forceinline__ void mma_tf32(float c[4],
                                         uint32_t a0, uint32_t a1,
                                         uint32_t a2, uint32_t a3,
                                         uint32_t b0, uint32_t b1) {
    asm volatile(
        "mma.sync.aligned.m16n8k8.row.col.f32.tf32.tf32.f32 "
        "{%0,%1,%2,%3}, {%4,%5,%6,%7}, {%8,%9}, {%0,%1,%2,%3};\n"
        : "+f"(c[0]), "+f"(c[1]), "+f"(c[2]), "+f"(c[3])
        : "r"(a0), "r"(a1), "r"(a2), "r"(a3), "r"(b0), "r"(b1));
}

__device__ __forceinline__ void cp16(uint32_t smem_u32, const float* gptr) {
    asm volatile("cp.async.cg.shared.global [%0], [%1], 16;\n"
                 :: "r"(smem_u32), "l"(gptr));
}
#define CP_COMMIT() asm volatile("cp.async.commit_group;\n" ::: "memory")
#define CP_WAIT0()  asm volatile("cp.async.wait_group 0;\n" ::: "memory")

// ---------------------------------------------------------------------------
// pre-round fp32 -> tf32 (RNA), vectorized
// ---------------------------------------------------------------------------
__global__ __launch_bounds__(256) void round_tf32_kernel(
    const float4* __restrict__ in, float4* __restrict__ out, int n4)
{
    int i = blockIdx.x * blockDim.x + threadIdx.x;
    if (i < n4) {
        float4 v = in[i];
        v.x = tf32r(v.x); v.y = tf32r(v.y);
        v.z = tf32r(v.z); v.w = tf32r(v.w);
        out[i] = v;
    }
}

// ---------------------------------------------------------------------------
// GEMM: C[M,N] = A[M,K] @ B[N,K]^T + bias[N]   (inputs pre-rounded tf32)
// CTA 128x128, 128 threads (4 warps x 64x64), K-step 32, 2-stage cp.async.
// ---------------------------------------------------------------------------
#define GS 36
#define G_STAGE_FL (2 * 128 * GS)   // floats per stage (A tile + B tile)
#define GEMM_SMEM_BYTES (2 * G_STAGE_FL * 4)

__device__ __forceinline__ void gemm_load_stage(
    uint32_t sb, int st, const float* __restrict__ A,
    const float* __restrict__ B, int bm, int bn, int K, int k0, int t)
{
    uint32_t abase = sb + st * G_STAGE_FL * 4;
    uint32_t bbase = abase + 128 * GS * 4;
#pragma unroll
    for (int l = 0; l < 8; l++) {
        int idx = t + l * 128;
        int r = idx >> 3, c4 = (idx & 7) * 4;
        cp16(abase + (r * GS + c4) * 4, A + (size_t)(bm + r) * K + k0 + c4);
    }
#pragma unroll
    for (int l = 0; l < 8; l++) {
        int idx = t + l * 128;
        int r = idx >> 3, c4 = (idx & 7) * 4;
        cp16(bbase + (r * GS + c4) * 4, B + (size_t)(bn + r) * K + k0 + c4);
    }
}

__global__ __launch_bounds__(128, 2) void gemm_tf32_kernel(
    const float* __restrict__ A, const float* __restrict__ B,
    const float* __restrict__ bias, float* __restrict__ C,
    int M, int N, int K, int rnd)
{
    extern __shared__ float sm[];
    const uint32_t sb = (uint32_t)__cvta_generic_to_shared(sm);

    const int t    = threadIdx.x;
    const int w    = t >> 5;
    const int lane = t & 31;
    const int g    = lane >> 2;
    const int tq   = lane & 3;
    const int wm   = w >> 1;   // 0..1
    const int wn   = w & 1;    // 0..1
    const int bm   = blockIdx.y * 128;
    const int bn   = blockIdx.x * 128;

    float acc[4][8][4];
#pragma unroll
    for (int i = 0; i < 4; i++)
#pragma unroll
        for (int j = 0; j < 8; j++)
#pragma unroll
            for (int r = 0; r < 4; r++) acc[i][j][r] = 0.f;

    gemm_load_stage(sb, 0, A, B, bm, bn, K, 0, t);
    CP_COMMIT();

    for (int k0 = 0; k0 < K; k0 += 32) {
        const int cur = (k0 >> 5) & 1;
        CP_WAIT0();
        __syncthreads();
        if (k0 + 32 < K) {
            gemm_load_stage(sb, cur ^ 1, A, B, bm, bn, K, k0 + 32, t);
            CP_COMMIT();
        }
        const float* As = sm + cur * G_STAGE_FL;
        const float* Bs = As + 128 * GS;

#pragma unroll
        for (int ks = 0; ks < 4; ks++) {
            const int kk = ks * 8;
            uint32_t a[4][4], b[8][2];
#pragma unroll
            for (int i = 0; i < 4; i++) {
                const float* ar = As + (wm * 64 + i * 16 + g) * GS + kk + tq;
                a[i][0] = __float_as_uint(ar[0]);
                a[i][1] = __float_as_uint(ar[8 * GS]);
                a[i][2] = __float_as_uint(ar[4]);
                a[i][3] = __float_as_uint(ar[8 * GS + 4]);
            }
#pragma unroll
            for (int j = 0; j < 8; j++) {
                const float* br = Bs + (wn * 64 + j * 8 + g) * GS + kk + tq;
                b[j][0] = __float_as_uint(br[0]);
                b[j][1] = __float_as_uint(br[4]);
            }
#pragma unroll
            for (int i = 0; i < 4; i++)
#pragma unroll
                for (int j = 0; j < 8; j++)
                    mma_tf32(acc[i][j], a[i][0], a[i][1], a[i][2], a[i][3],
                             b[j][0], b[j][1]);
        }
        // top-of-loop barrier protects smem reuse
    }

    // epilogue: bias (+ optional tf32 rounding for downstream consumers)
#pragma unroll
    for (int i = 0; i < 4; i++) {
        int row0 = bm + wm * 64 + i * 16 + g;
#pragma unroll
        for (int j = 0; j < 8; j++) {
            int col0 = bn + wn * 64 + j * 8 + 2 * tq;
            float b0 = bias[col0], b1 = bias[col0 + 1];
            float v00 = acc[i][j][0] + b0, v01 = acc[i][j][1] + b1;
            float v10 = acc[i][j][2] + b0, v11 = acc[i][j][3] + b1;
            if (rnd) { v00 = tf32r(v00); v01 = tf32r(v01);
                       v10 = tf32r(v10); v11 = tf32r(v11); }
            *(float2*)(C + (size_t)row0 * N + col0)       = make_float2(v00, v01);
            *(float2*)(C + (size_t)(row0 + 8) * N + col0) = make_float2(v10, v11);
        }
    }
}

// ---------------------------------------------------------------------------
// Fused attention: 128-query tile/CTA, 8 warps x 16 rows, double-buffered K/V.
// scores = (2 q_i.k_j - |q_i|^2 - |k_j|^2)*0.125 <= ~0 -> softmax w/o max.
// Q fragments live in registers for the whole kernel; S is per-warp chunked.
// Inputs pre-rounded tf32; output written tf32-rounded (feeds O-proj GEMM).
// ---------------------------------------------------------------------------
#define QSd 68
#define VSd 72
#define SWS 68
#define OFF_QS  0
#define OFF_KS  (128 * QSd)                    // Q staging ends
#define OFF_VS  (OFF_KS + 2 * 128 * QSd)
#define OFF_SW  (OFF_VS + 2 * 128 * VSd)
#define OFF_SQI (OFF_SW + 8 * 16 * SWS)
#define OFF_SQJ (OFF_SQI + 128)
#define ATT_SMEM_FLOATS (OFF_SQJ + 128)        // 53504 floats = 214016 B

__global__ __launch_bounds__(256, 1) void attn_tf32_kernel(
    const float* __restrict__ q, const float* __restrict__ v,
    float* __restrict__ o)
{
    extern __shared__ float sm[];
    const uint32_t sb = (uint32_t)__cvta_generic_to_shared(sm);
    float* Qs  = sm;
    float* Sw  = sm + OFF_SW;
    float* sqi = sm + OFF_SQI;
    float* sqj = sm + OFF_SQJ;

    const int bh = blockIdx.y;
    const int b  = bh >> 4;
    const int h  = bh & 15;
    const int qt = blockIdx.x * 128;
    const int t    = threadIdx.x;
    const int w    = t >> 5;
    const int lane = t & 31;
    const int g    = lane >> 2;
    const int tq   = lane & 3;
    const int i0   = 16 * w;

    const float* qbase = q + (size_t)b * 1024 * DIM + h * 64;
    const float* vbase = v + (size_t)b * 1024 * DIM + h * 64;

    // prefetch K/V tile 0 into stage 0
#pragma unroll
    for (int l = 0; l < 8; l++) {
        int idx = t + l * 256;
        int r = idx >> 4, c4 = (idx & 15) * 4;
        cp16(sb + (OFF_KS + r * QSd + c4) * 4, qbase + (size_t)r * DIM + c4);
        cp16(sb + (OFF_VS + r * VSd + c4) * 4, vbase + (size_t)r * DIM + c4);
    }
    CP_COMMIT();

    // stage Q tile (pre-rounded in gmem), plain copy
#pragma unroll
    for (int l = 0; l < 8; l++) {
        int idx = t + l * 256;
        int r = idx >> 4, c4 = (idx & 15) * 4;
        *(float4*)(Qs + r * QSd + c4) =
            *(const float4*)(qbase + (size_t)(qt + r) * DIM + c4);
    }
    __syncthreads();
    if (t < 128) {
        float s = 0.f;
#pragma unroll
        for (int k = 0; k < 64; k++) { float xx = Qs[t * QSd + k]; s = fmaf(xx, xx, s); }
        sqi[t] = s;
    }
    // hoist Q fragments (whole kernel lifetime)
    uint32_t qa[8][4];
#pragma unroll
    for (int ks = 0; ks < 8; ks++) {
        const float* qr = Qs + (i0 + g) * QSd + ks * 8 + tq;
        qa[ks][0] = __float_as_uint(qr[0]);
        qa[ks][1] = __float_as_uint(qr[8 * QSd]);
        qa[ks][2] = __float_as_uint(qr[4]);
        qa[ks][3] = __float_as_uint(qr[8 * QSd + 4]);
    }
    __syncthreads();
    const float si_lo = sqi[i0 + g];
    const float si_hi = sqi[i0 + 8 + g];

    float oacc[8][4];
#pragma unroll
    for (int j = 0; j < 8; j++)
#pragma unroll
        for (int r = 0; r < 4; r++) oacc[j][r] = 0.f;
    float den_lo = 0.f, den_hi = 0.f;
    const float scale = 0.125f;
    float* Swb = Sw + w * (16 * SWS);

    for (int kt = 0, it = 0; kt < 1024; kt += 128, it++) {
        const int cur = it & 1;
        CP_WAIT0();
        __syncthreads();
        if (kt + 128 < 1024) {
            const int nk = OFF_KS + (cur ^ 1) * 128 * QSd;
            const int nv = OFF_VS + (cur ^ 1) * 128 * VSd;
#pragma unroll
            for (int l = 0; l < 8; l++) {
                int idx = t + l * 256;
                int r = idx >> 4, c4 = (idx & 15) * 4;
                cp16(sb + (nk + r * QSd + c4) * 4,
                     qbase + (size_t)(kt + 128 + r) * DIM + c4);
                cp16(sb + (nv + r * VSd + c4) * 4,
                     vbase + (size_t)(kt + 128 + r) * DIM + c4);
            }
            CP_COMMIT();
        }
        const float* Ksc = sm + OFF_KS + cur * 128 * QSd;
        const float* Vsc = sm + OFF_VS + cur * 128 * VSd;
        if (t < 128) {
            float s = 0.f;
#pragma unroll
            for (int k = 0; k < 64; k++) { float xx = Ksc[t * QSd + k]; s = fmaf(xx, xx, s); }
            sqj[t] = s;
        }
        __syncthreads();

#pragma unroll
        for (int jc = 0; jc < 4; jc++) {
            const int par = (jc & 1) * 32;
            float c[4][4];
#pragma unroll
            for (int jj = 0; jj < 4; jj++)
#pragma unroll
                for (int r = 0; r < 4; r++) c[jj][r] = 0.f;

#pragma unroll
            for (int ks = 0; ks < 8; ks++) {
#pragma unroll
                for (int jj = 0; jj < 4; jj++) {
                    const float* kr = Ksc + ((jc * 4 + jj) * 8 + g) * QSd + ks * 8 + tq;
                    mma_tf32(c[jj], qa[ks][0], qa[ks][1], qa[ks][2], qa[ks][3],
                             __float_as_uint(kr[0]), __float_as_uint(kr[4]));
                }
            }
            // exp + round + per-warp S chunk store + denom
#pragma unroll
            for (int jj = 0; jj < 4; jj++) {
                int cb = jj * 8 + 2 * tq;
                float sj0 = sqj[jc * 32 + cb], sj1 = sqj[jc * 32 + cb + 1];
                float e00 = tf32r(__expf((2.f * c[jj][0] - si_lo - sj0) * scale));
                float e01 = tf32r(__expf((2.f * c[jj][1] - si_lo - sj1) * scale));
                float e10 = tf32r(__expf((2.f * c[jj][2] - si_hi - sj0) * scale));
                float e11 = tf32r(__expf((2.f * c[jj][3] - si_hi - sj1) * scale));
                den_lo += e00 + e01;
                den_hi += e10 + e11;
                *(float2*)(Swb + g * SWS + par + cb)       = make_float2(e00, e01);
                *(float2*)(Swb + (g + 8) * SWS + par + cb) = make_float2(e10, e11);
            }
            __syncwarp();
            // PV over this 32-key chunk
#pragma unroll
            for (int ksl = 0; ksl < 4; ksl++) {
                const float* sr = Swb + g * SWS + par + ksl * 8 + tq;
                uint32_t a0 = __float_as_uint(sr[0]);
                uint32_t a1 = __float_as_uint(sr[8 * SWS]);
                uint32_t a2 = __float_as_uint(sr[4]);
                uint32_t a3 = __float_as_uint(sr[8 * SWS + 4]);
                const int vrow = jc * 32 + ksl * 8 + tq;
#pragma unroll
                for (int j = 0; j < 8; j++) {
                    uint32_t b0 = __float_as_uint(Vsc[vrow * VSd + j * 8 + g]);
                    uint32_t b1 = __float_as_uint(Vsc[(vrow + 4) * VSd + j * 8 + g]);
                    mma_tf32(oacc[j], a0, a1, a2, a3, b0, b1);
                }
            }
        }
    }

    den_lo += __shfl_xor_sync(0xffffffffu, den_lo, 1);
    den_lo += __shfl_xor_sync(0xffffffffu, den_lo, 2);
    den_hi += __shfl_xor_sync(0xffffffffu, den_hi, 1);
    den_hi += __shfl_xor_sync(0xffffffffu, den_hi, 2);
    const float inv_lo = 1.f / den_lo;
    const float inv_hi = 1.f / den_hi;

    float* orow_lo = o + (size_t)(b * 1024 + qt + i0 + g) * DIM + h * 64;
    float* orow_hi = o + (size_t)(b * 1024 + qt + i0 + 8 + g) * DIM + h * 64;
#pragma unroll
    for (int j = 0; j < 8; j++) {
        int col = j * 8 + 2 * tq;
        *(float2*)(orow_lo + col) = make_float2(tf32r(oacc[j][0] * inv_lo),
                                                tf32r(oacc[j][1] * inv_lo));
        *(float2*)(orow_hi + col) = make_float2(tf32r(oacc[j][2] * inv_hi),
                                                tf32r(oacc[j][3] * inv_hi));
    }
}

// ---------------------------------------------------------------------------
extern "C" void kernel_launch(void* const* d_in, const int* in_sizes, int n_in,
                              void* d_out, int out_size)
{
    const float* x  = (const float*)d_in[0];
    const float* Wq = (const float*)d_in[1];
    const float* bq = (const float*)d_in[2];
    const float* Wv = (const float*)d_in[3];
    const float* bv = (const float*)d_in[4];
    const float* Wo = (const float*)d_in[5];
    const float* bo = (const float*)d_in[6];
    float* out = (float*)d_out;

    float *qp, *vp, *ap, *xp, *wqp, *wvp, *wop;
    cudaGetSymbolAddress((void**)&qp,  g_q);
    cudaGetSymbolAddress((void**)&vp,  g_v);
    cudaGetSymbolAddress((void**)&ap,  g_a);
    cudaGetSymbolAddress((void**)&xp,  g_x);
    cudaGetSymbolAddress((void**)&wqp, g_wq);
    cudaGetSymbolAddress((void**)&wvp, g_wv);
    cudaGetSymbolAddress((void**)&wop, g_wo);

    cudaFuncSetAttribute(gemm_tf32_kernel,
                         cudaFuncAttributeMaxDynamicSharedMemorySize,
                         GEMM_SMEM_BYTES);
    cudaFuncSetAttribute(attn_tf32_kernel,
                         cudaFuncAttributeMaxDynamicSharedMemorySize,
                         (int)(ATT_SMEM_FLOATS * sizeof(float)));

    // pre-round inputs to tf32 once
    round_tf32_kernel<<<4096, 256>>>((const float4*)x,  (float4*)xp,  M_ROWS * DIM / 4);
    round_tf32_kernel<<<1024, 256>>>((const float4*)Wq, (float4*)wqp, DIM * DIM / 4);
    round_tf32_kernel<<<1024, 256>>>((const float4*)Wv, (float4*)wvp, DIM * DIM / 4);
    round_tf32_kernel<<<1024, 256>>>((const float4*)Wo, (float4*)wop, DIM * DIM / 4);

    dim3 ggrid(DIM / 128, M_ROWS / 128);   // (8, 32)
    gemm_tf32_kernel<<<ggrid, 128, GEMM_SMEM_BYTES>>>(xp, wqp, bq, qp,
                                                      M_ROWS, DIM, DIM, 1);
    gemm_tf32_kernel<<<ggrid, 128, GEMM_SMEM_BYTES>>>(xp, wvp, bv, vp,
                                                      M_ROWS, DIM, DIM, 1);
    attn_tf32_kernel<<<dim3(8, 64), 256, ATT_SMEM_FLOATS * sizeof(float)>>>(qp, vp, ap);
    gemm_tf32_kernel<<<ggrid, 128, GEMM_SMEM_BYTES>>>(ap, wop, bo, out,
                                                      M_ROWS, DIM, DIM, 0);
}

// round 5
// speedup vs baseline: 4.9829x; 1.0563x over previous
#include <cuda_runtime.h>
#include <cstdint>

// ---------------------------------------------------------------------------
// L2Attention via tf32 mma.sync (m16n8k8). 2-CTA/SM occupancy everywhere.
// b=4, n=1024, dim=1024, heads=16, d=64
// ---------------------------------------------------------------------------

#define M_ROWS 4096
#define DIM    1024

__device__ float g_q[M_ROWS * DIM];
__device__ float g_v[M_ROWS * DIM];
__device__ float g_a[M_ROWS * DIM];
__device__ float g_x[M_ROWS * DIM];
__device__ float g_wq[DIM * DIM];
__device__ float g_wv[DIM * DIM];
__device__ float g_wo[DIM * DIM];
__device__ float g_sq[64 * 1024];     // |q|^2 per (b,h,n)

__device__ __forceinline__ float tf32r(float x) {
    uint32_t u;
    asm("cvt.rna.tf32.f32 %0, %1;" : "=r"(u) : "f"(x));
    return __uint_as_float(u);
}

__device__ __forceinline__ void mma_tf32(float c[4],
                                         uint32_t a0, uint32_t a1,
                                         uint32_t a2, uint32_t a3,
                                         uint32_t b0, uint32_t b1) {
    asm volatile(
        "mma.sync.aligned.m16n8k8.row.col.f32.tf32.tf32.f32 "
        "{%0,%1,%2,%3}, {%4,%5,%6,%7}, {%8,%9}, {%0,%1,%2,%3};\n"
        : "+f"(c[0]), "+f"(c[1]), "+f"(c[2]), "+f"(c[3])
        : "r"(a0), "r"(a1), "r"(a2), "r"(a3), "r"(b0), "r"(b1));
}

__device__ __forceinline__ void cp16(uint32_t smem_u32, const float* gptr) {
    asm volatile("cp.async.cg.shared.global [%0], [%1], 16;\n"
                 :: "r"(smem_u32), "l"(gptr));
}
#define CP_COMMIT() asm volatile("cp.async.commit_group;\n" ::: "memory")
#define CP_WAIT0()  asm volatile("cp.async.wait_group 0;\n" ::: "memory")

// ---------------------------------------------------------------------------
// one launch: round x + Wq + Wv + Wo to tf32 (RNA)
// ---------------------------------------------------------------------------
__global__ __launch_bounds__(256) void round_all_kernel(
    const float4* __restrict__ x,  float4* __restrict__ xo,
    const float4* __restrict__ w0, float4* __restrict__ w0o,
    const float4* __restrict__ w1, float4* __restrict__ w1o,
    const float4* __restrict__ w2, float4* __restrict__ w2o)
{
    int i = blockIdx.x * 256 + threadIdx.x;   // grid covers 1048576
    {
        float4 v = x[i];
        v.x = tf32r(v.x); v.y = tf32r(v.y);
        v.z = tf32r(v.z); v.w = tf32r(v.w);
        xo[i] = v;
    }
    if (i < 262144) {
        float4 a = w0[i], b = w1[i], c = w2[i];
        a.x = tf32r(a.x); a.y = tf32r(a.y); a.z = tf32r(a.z); a.w = tf32r(a.w);
        b.x = tf32r(b.x); b.y = tf32r(b.y); b.z = tf32r(b.z); b.w = tf32r(b.w);
        c.x = tf32r(c.x); c.y = tf32r(c.y); c.z = tf32r(c.z); c.w = tf32r(c.w);
        w0o[i] = a; w1o[i] = b; w2o[i] = c;
    }
}

// ---------------------------------------------------------------------------
// |q|^2 table: sqg[(b*16+h)*1024 + n] = sum_d q[b*1024+n][h*64+d]^2
// ---------------------------------------------------------------------------
__global__ __launch_bounds__(256) void sq_kernel(
    const float* __restrict__ q, float* __restrict__ sqg)
{
    int o  = blockIdx.x * 256 + threadIdx.x;  // 65536
    int n  = o & 1023;
    int bh = o >> 10;
    int b  = bh >> 4, h = bh & 15;
    const float4* p = (const float4*)(q + ((size_t)(b * 1024 + n)) * DIM + h * 64);
    float s = 0.f;
#pragma unroll
    for (int i = 0; i < 16; i++) {
        float4 v = p[i];
        s += v.x * v.x + v.y * v.y + v.z * v.z + v.w * v.w;
    }
    sqg[o] = s;
}

// ---------------------------------------------------------------------------
// GEMM: C[M,N] = A[M,K] @ B[N,K]^T + bias   (torch Linear, tf32 inputs)
// 256 thr, 8 warps (4M x 2N), warp tile 32x64, K-step 32, 2-stage cp.async.
// blockIdx.z selects (B0,bias0,C0) vs (B1,bias1,C1)  -> fused Q/V projection.
// ---------------------------------------------------------------------------
#define GS 36
#define G_STAGE (2 * 128 * GS)            // floats per stage
#define GEMM_SMEM (2 * G_STAGE * 4)       // 73728 B

__device__ __forceinline__ void g_load(
    uint32_t sb, int st, const float* __restrict__ A,
    const float* __restrict__ B, int bm, int bn, int K, int k0, int t)
{
    uint32_t ab = sb + st * G_STAGE * 4;
    uint32_t bb = ab + 128 * GS * 4;
#pragma unroll
    for (int l = 0; l < 4; l++) {
        int idx = t + l * 256;
        int r = idx >> 3, c4 = (idx & 7) * 4;
        cp16(ab + (r * GS + c4) * 4, A + (size_t)(bm + r) * K + k0 + c4);
    }
#pragma unroll
    for (int l = 0; l < 4; l++) {
        int idx = t + l * 256;
        int r = idx >> 3, c4 = (idx & 7) * 4;
        cp16(bb + (r * GS + c4) * 4, B + (size_t)(bn + r) * K + k0 + c4);
    }
    CP_COMMIT();
}

__global__ __launch_bounds__(256, 2) void gemm_tf32_kernel(
    const float* __restrict__ A,
    const float* __restrict__ B0, const float* __restrict__ bias0,
    float* __restrict__ C0,
    const float* __restrict__ B1, const float* __restrict__ bias1,
    float* __restrict__ C1,
    int N, int K, int rnd)
{
    extern __shared__ float sm[];
    const uint32_t sb = (uint32_t)__cvta_generic_to_shared(sm);

    const float* B    = blockIdx.z ? B1 : B0;
    const float* bias = blockIdx.z ? bias1 : bias0;
    float*       C    = blockIdx.z ? C1 : C0;

    const int t    = threadIdx.x;
    const int w    = t >> 5;
    const int lane = t & 31;
    const int g    = lane >> 2;
    const int tq   = lane & 3;
    const int wm   = w & 3;    // 0..3 -> 32-row group
    const int wn   = w >> 2;   // 0..1 -> 64-col group
    const int bm   = blockIdx.y * 128;
    const int bn   = blockIdx.x * 128;

    float acc[2][8][4];
#pragma unroll
    for (int i = 0; i < 2; i++)
#pragma unroll
        for (int j = 0; j < 8; j++)
#pragma unroll
            for (int r = 0; r < 4; r++) acc[i][j][r] = 0.f;

    g_load(sb, 0, A, B, bm, bn, K, 0, t);

    for (int k0 = 0; k0 < K; k0 += 32) {
        const int cur = (k0 >> 5) & 1;
        CP_WAIT0();
        __syncthreads();
        if (k0 + 32 < K)
            g_load(sb, cur ^ 1, A, B, bm, bn, K, k0 + 32, t);

        const float* As = sm + cur * G_STAGE;
        const float* Bs = As + 128 * GS;

#pragma unroll
        for (int ks = 0; ks < 4; ks++) {
            const int kk = ks * 8;
            uint32_t a[2][4], b[8][2];
#pragma unroll
            for (int i = 0; i < 2; i++) {
                const float* ar = As + (wm * 32 + i * 16 + g) * GS + kk + tq;
                a[i][0] = __float_as_uint(ar[0]);
                a[i][1] = __float_as_uint(ar[8 * GS]);
                a[i][2] = __float_as_uint(ar[4]);
                a[i][3] = __float_as_uint(ar[8 * GS + 4]);
            }
#pragma unroll
            for (int j = 0; j < 8; j++) {
                const float* br = Bs + (wn * 64 + j * 8 + g) * GS + kk + tq;
                b[j][0] = __float_as_uint(br[0]);
                b[j][1] = __float_as_uint(br[4]);
            }
#pragma unroll
            for (int i = 0; i < 2; i++)
#pragma unroll
                for (int j = 0; j < 8; j++)
                    mma_tf32(acc[i][j], a[i][0], a[i][1], a[i][2], a[i][3],
                             b[j][0], b[j][1]);
        }
    }

#pragma unroll
    for (int i = 0; i < 2; i++) {
        int row0 = bm + wm * 32 + i * 16 + g;
#pragma unroll
        for (int j = 0; j < 8; j++) {
            int col0 = bn + wn * 64 + j * 8 + 2 * tq;
            float b0 = bias[col0], b1 = bias[col0 + 1];
            float v00 = acc[i][j][0] + b0, v01 = acc[i][j][1] + b1;
            float v10 = acc[i][j][2] + b0, v11 = acc[i][j][3] + b1;
            if (rnd) { v00 = tf32r(v00); v01 = tf32r(v01);
                       v10 = tf32r(v10); v11 = tf32r(v11); }
            *(float2*)(C + (size_t)row0 * N + col0)       = make_float2(v00, v01);
            *(float2*)(C + (size_t)(row0 + 8) * N + col0) = make_float2(v10, v11);
        }
    }
}

// ---------------------------------------------------------------------------
// Fused attention: 128-query tile, 8 warps x 16 rows, single-buffered K/V
// (2 CTAs/SM cover load latency), |q|^2 from precomputed table.
// scores = (2 q_i.k_j - |q_i|^2 - |k_j|^2)*0.125 <= ~0 -> softmax w/o max.
// ---------------------------------------------------------------------------
#define SWS 68                       // K / S / staged-Q row stride
#define VSd 72                       // V row stride
#define OFF_K  0                     // 128*68 = 8704 floats
#define OFF_V  8704                  // 128*72 = 9216
#define OFF_S  (8704 + 9216)         // 8704 (also Q staging in prologue)
#define OFF_SQ (OFF_S + 8704)        // 1024
#define ATT_FL (OFF_SQ + 1024)       // 27648 floats = 110592 B

__global__ __launch_bounds__(256, 2) void attn_tf32_kernel(
    const float* __restrict__ q, const float* __restrict__ v,
    const float* __restrict__ sqg, float* __restrict__ o)
{
    extern __shared__ float sm[];
    const uint32_t sb = (uint32_t)__cvta_generic_to_shared(sm);

    const int bh = blockIdx.y;
    const int b  = bh >> 4;
    const int h  = bh & 15;
    const int qt = blockIdx.x * 128;
    const int t    = threadIdx.x;
    const int w    = t >> 5;
    const int lane = t & 31;
    const int g    = lane >> 2;
    const int tq   = lane & 3;
    const int i0   = 16 * w;

    const float* qbase = q + (size_t)b * 1024 * DIM + h * 64;
    const float* vbase = v + (size_t)b * 1024 * DIM + h * 64;

    // prefetch K/V tile 0
#pragma unroll
    for (int l = 0; l < 8; l++) {
        int idx = t + l * 256;
        int r = idx >> 4, c4 = (idx & 15) * 4;
        cp16(sb + (OFF_K + r * SWS + c4) * 4, qbase + (size_t)r * DIM + c4);
        cp16(sb + (OFF_V + r * VSd + c4) * 4, vbase + (size_t)r * DIM + c4);
    }
    CP_COMMIT();

    // |q|^2 table for this (b,h): 1024 floats
    ((float4*)(sm + OFF_SQ))[t] = ((const float4*)(sqg + (size_t)bh * 1024))[t];

    // stage Q tile into the S region (transient)
    float* Qs = sm + OFF_S;
#pragma unroll
    for (int l = 0; l < 8; l++) {
        int idx = t + l * 256;
        int r = idx >> 4, c4 = (idx & 15) * 4;
        *(float4*)(Qs + r * SWS + c4) =
            *(const float4*)(qbase + (size_t)(qt + r) * DIM + c4);
    }
    __syncthreads();

    uint32_t qa[8][4];
#pragma unroll
    for (int ks = 0; ks < 8; ks++) {
        const float* qr = Qs + (i0 + g) * SWS + ks * 8 + tq;
        qa[ks][0] = __float_as_uint(qr[0]);
        qa[ks][1] = __float_as_uint(qr[8 * SWS]);
        qa[ks][2] = __float_as_uint(qr[4]);
        qa[ks][3] = __float_as_uint(qr[8 * SWS + 4]);
    }
    const float* sqa = sm + OFF_SQ;
    const float si_lo = sqa[qt + i0 + g];
    const float si_hi = sqa[qt + i0 + 8 + g];

    CP_WAIT0();
    __syncthreads();   // K0/V0 ready; Q staging fully consumed -> S reusable

    float oacc[8][4];
#pragma unroll
    for (int j = 0; j < 8; j++)
#pragma unroll
        for (int r = 0; r < 4; r++) oacc[j][r] = 0.f;
    float den_lo = 0.f, den_hi = 0.f;
    const float scale = 0.125f;
    float* Swb = sm + OFF_S + w * (16 * SWS);
    const float* Ksc = sm + OFF_K;
    const float* Vsc = sm + OFF_V;

    for (int kt = 0; kt < 1024; kt += 128) {
        const float* sqk = sqa + kt;

#pragma unroll
        for (int jc = 0; jc < 4; jc++) {
            const int par = (jc & 1) * 32;
            float c[4][4];
#pragma unroll
            for (int jj = 0; jj < 4; jj++)
#pragma unroll
                for (int r = 0; r < 4; r++) c[jj][r] = 0.f;

#pragma unroll
            for (int ks = 0; ks < 8; ks++) {
#pragma unroll
                for (int jj = 0; jj < 4; jj++) {
                    const float* kr = Ksc + ((jc * 4 + jj) * 8 + g) * SWS + ks * 8 + tq;
                    mma_tf32(c[jj], qa[ks][0], qa[ks][1], qa[ks][2], qa[ks][3],
                             __float_as_uint(kr[0]), __float_as_uint(kr[4]));
                }
            }
#pragma unroll
            for (int jj = 0; jj < 4; jj++) {
                int cb = jj * 8 + 2 * tq;
                float sj0 = sqk[jc * 32 + cb], sj1 = sqk[jc * 32 + cb + 1];
                float e00 = tf32r(__expf((2.f * c[jj][0] - si_lo - sj0) * scale));
                float e01 = tf32r(__expf((2.f * c[jj][1] - si_lo - sj1) * scale));
                float e10 = tf32r(__expf((2.f * c[jj][2] - si_hi - sj0) * scale));
                float e11 = tf32r(__expf((2.f * c[jj][3] - si_hi - sj1) * scale));
                den_lo += e00 + e01;
                den_hi += e10 + e11;
                *(float2*)(Swb + g * SWS + par + cb)       = make_float2(e00, e01);
                *(float2*)(Swb + (g + 8) * SWS + par + cb) = make_float2(e10, e11);
            }
            __syncwarp();
#pragma unroll
            for (int ksl = 0; ksl < 4; ksl++) {
                const float* sr = Swb + g * SWS + par + ksl * 8 + tq;
                uint32_t a0 = __float_as_uint(sr[0]);
                uint32_t a1 = __float_as_uint(sr[8 * SWS]);
                uint32_t a2 = __float_as_uint(sr[4]);
                uint32_t a3 = __float_as_uint(sr[8 * SWS + 4]);
                const int vrow = jc * 32 + ksl * 8 + tq;
#pragma unroll
                for (int j = 0; j < 8; j++) {
                    uint32_t b0 = __float_as_uint(Vsc[vrow * VSd + j * 8 + g]);
                    uint32_t b1 = __float_as_uint(Vsc[(vrow + 4) * VSd + j * 8 + g]);
                    mma_tf32(oacc[j], a0, a1, a2, a3, b0, b1);
                }
            }
        }
        __syncthreads();   // all warps done with K/V buffers

        if (kt + 128 < 1024) {
#pragma unroll
            for (int l = 0; l < 8; l++) {
                int idx = t + l * 256;
                int r = idx >> 4, c4 = (idx & 15) * 4;
                cp16(sb + (OFF_K + r * SWS + c4) * 4,
                     qbase + (size_t)(kt + 128 + r) * DIM + c4);
                cp16(sb + (OFF_V + r * VSd + c4) * 4,
                     vbase + (size_t)(kt + 128 + r) * DIM + c4);
            }
            CP_COMMIT();
            CP_WAIT0();
            __syncthreads();   // next K/V visible to all
        }
    }

    den_lo += __shfl_xor_sync(0xffffffffu, den_lo, 1);
    den_lo += __shfl_xor_sync(0xffffffffu, den_lo, 2);
    den_hi += __shfl_xor_sync(0xffffffffu, den_hi, 1);
    den_hi += __shfl_xor_sync(0xffffffffu, den_hi, 2);
    const float inv_lo = 1.f / den_lo;
    const float inv_hi = 1.f / den_hi;

    float* orow_lo = o + (size_t)(b * 1024 + qt + i0 + g) * DIM + h * 64;
    float* orow_hi = o + (size_t)(b * 1024 + qt + i0 + 8 + g) * DIM + h * 64;
#pragma unroll
    for (int j = 0; j < 8; j++) {
        int col = j * 8 + 2 * tq;
        *(float2*)(orow_lo + col) = make_float2(tf32r(oacc[j][0] * inv_lo),
                                                tf32r(oacc[j][1] * inv_lo));
        *(float2*)(orow_hi + col) = make_float2(tf32r(oacc[j][2] * inv_hi),
                                                tf32r(oacc[j][3] * inv_hi));
    }
}

// ---------------------------------------------------------------------------
extern "C" void kernel_launch(void* const* d_in, const int* in_sizes, int n_in,
                              void* d_out, int out_size)
{
    const float* x  = (const float*)d_in[0];
    const float* Wq = (const float*)d_in[1];
    const float* bq = (const float*)d_in[2];
    const float* Wv = (const float*)d_in[3];
    const float* bv = (const float*)d_in[4];
    const float* Wo = (const float*)d_in[5];
    const float* bo = (const float*)d_in[6];
    float* out = (float*)d_out;

    float *qp, *vp, *ap, *xp, *wqp, *wvp, *wop, *sqp;
    cudaGetSymbolAddress((void**)&qp,  g_q);
    cudaGetSymbolAddress((void**)&vp,  g_v);
    cudaGetSymbolAddress((void**)&ap,  g_a);
    cudaGetSymbolAddress((void**)&xp,  g_x);
    cudaGetSymbolAddress((void**)&wqp, g_wq);
    cudaGetSymbolAddress((void**)&wvp, g_wv);
    cudaGetSymbolAddress((void**)&wop, g_wo);
    cudaGetSymbolAddress((void**)&sqp, g_sq);

    cudaFuncSetAttribute(gemm_tf32_kernel,
                         cudaFuncAttributeMaxDynamicSharedMemorySize, GEMM_SMEM);
    cudaFuncSetAttribute(attn_tf32_kernel,
                         cudaFuncAttributeMaxDynamicSharedMemorySize,
                         (int)(ATT_FL * sizeof(float)));

    round_all_kernel<<<4096, 256>>>(
        (const float4*)x,  (float4*)xp,
        (const float4*)Wq, (float4*)wqp,
        (const float4*)Wv, (float4*)wvp,
        (const float4*)Wo, (float4*)wop);

    // fused Q + V projections (z selects weight/bias/output)
    gemm_tf32_kernel<<<dim3(8, 32, 2), 256, GEMM_SMEM>>>(
        xp, wqp, bq, qp, wvp, bv, vp, DIM, DIM, 1);

    sq_kernel<<<256, 256>>>(qp, sqp);

    attn_tf32_kernel<<<dim3(8, 64), 256, ATT_FL * sizeof(float)>>>(qp, vp, sqp, ap);

    gemm_tf32_kernel<<<dim3(8, 32, 1), 256, GEMM_SMEM>>>(
        ap, wop, bo, out, wop, bo, out, DIM, DIM, 0);
}

// round 6
// speedup vs baseline: 4.9987x; 1.0032x over previous
#include <cuda_runtime.h>
#include <cstdint>

// ---------------------------------------------------------------------------
// L2Attention via tf32 mma.sync (m16n8k8).
// Attention: 4 warps x 32 query rows -> B-fragment reuse x2 (1.5 LDS/MMA).
// b=4, n=1024, dim=1024, heads=16, d=64
// ---------------------------------------------------------------------------

#define M_ROWS 4096
#define DIM    1024

__device__ float g_q[M_ROWS * DIM];
__device__ float g_v[M_ROWS * DIM];
__device__ float g_a[M_ROWS * DIM];
__device__ float g_x[M_ROWS * DIM];
__device__ float g_wq[DIM * DIM];
__device__ float g_wv[DIM * DIM];
__device__ float g_wo[DIM * DIM];
__device__ float g_sq[64 * 1024];     // |q|^2 per (b,h,n)

__device__ __forceinline__ float tf32r(float x) {
    uint32_t u;
    asm("cvt.rna.tf32.f32 %0, %1;" : "=r"(u) : "f"(x));
    return __uint_as_float(u);
}

__device__ __forceinline__ void mma_tf32(float c[4],
                                         uint32_t a0, uint32_t a1,
                                         uint32_t a2, uint32_t a3,
                                         uint32_t b0, uint32_t b1) {
    asm volatile(
        "mma.sync.aligned.m16n8k8.row.col.f32.tf32.tf32.f32 "
        "{%0,%1,%2,%3}, {%4,%5,%6,%7}, {%8,%9}, {%0,%1,%2,%3};\n"
        : "+f"(c[0]), "+f"(c[1]), "+f"(c[2]), "+f"(c[3])
        : "r"(a0), "r"(a1), "r"(a2), "r"(a3), "r"(b0), "r"(b1));
}

__device__ __forceinline__ void cp16(uint32_t smem_u32, const float* gptr) {
    asm volatile("cp.async.cg.shared.global [%0], [%1], 16;\n"
                 :: "r"(smem_u32), "l"(gptr));
}
#define CP_COMMIT() asm volatile("cp.async.commit_group;\n" ::: "memory")
#define CP_WAIT0()  asm volatile("cp.async.wait_group 0;\n" ::: "memory")

// ---------------------------------------------------------------------------
// one launch: round x + Wq + Wv + Wo to tf32 (RNA)
// ---------------------------------------------------------------------------
__global__ __launch_bounds__(256) void round_all_kernel(
    const float4* __restrict__ x,  float4* __restrict__ xo,
    const float4* __restrict__ w0, float4* __restrict__ w0o,
    const float4* __restrict__ w1, float4* __restrict__ w1o,
    const float4* __restrict__ w2, float4* __restrict__ w2o)
{
    int i = blockIdx.x * 256 + threadIdx.x;
    {
        float4 v = x[i];
        v.x = tf32r(v.x); v.y = tf32r(v.y);
        v.z = tf32r(v.z); v.w = tf32r(v.w);
        xo[i] = v;
    }
    if (i < 262144) {
        float4 a = w0[i], b = w1[i], c = w2[i];
        a.x = tf32r(a.x); a.y = tf32r(a.y); a.z = tf32r(a.z); a.w = tf32r(a.w);
        b.x = tf32r(b.x); b.y = tf32r(b.y); b.z = tf32r(b.z); b.w = tf32r(b.w);
        c.x = tf32r(c.x); c.y = tf32r(c.y); c.z = tf32r(c.z); c.w = tf32r(c.w);
        w0o[i] = a; w1o[i] = b; w2o[i] = c;
    }
}

// ---------------------------------------------------------------------------
// |q|^2 table: sqg[(b*16+h)*1024 + n] = sum_d q[b*1024+n][h*64+d]^2
// ---------------------------------------------------------------------------
__global__ __launch_bounds__(256) void sq_kernel(
    const float* __restrict__ q, float* __restrict__ sqg)
{
    int o  = blockIdx.x * 256 + threadIdx.x;
    int n  = o & 1023;
    int bh = o >> 10;
    int b  = bh >> 4, h = bh & 15;
    const float4* p = (const float4*)(q + ((size_t)(b * 1024 + n)) * DIM + h * 64);
    float s = 0.f;
#pragma unroll
    for (int i = 0; i < 16; i++) {
        float4 v = p[i];
        s += v.x * v.x + v.y * v.y + v.z * v.z + v.w * v.w;
    }
    sqg[o] = s;
}

// ---------------------------------------------------------------------------
// GEMM (unchanged from R5): 256 thr, 8 warps (4M x 2N), tile 128x128,
// K-step 32, 2-stage cp.async. blockIdx.z selects output -> fused Q/V proj.
// ---------------------------------------------------------------------------
#define GS 36
#define G_STAGE (2 * 128 * GS)
#define GEMM_SMEM (2 * G_STAGE * 4)

__device__ __forceinline__ void g_load(
    uint32_t sb, int st, const float* __restrict__ A,
    const float* __restrict__ B, int bm, int bn, int K, int k0, int t)
{
    uint32_t ab = sb + st * G_STAGE * 4;
    uint32_t bb = ab + 128 * GS * 4;
#pragma unroll
    for (int l = 0; l < 4; l++) {
        int idx = t + l * 256;
        int r = idx >> 3, c4 = (idx & 7) * 4;
        cp16(ab + (r * GS + c4) * 4, A + (size_t)(bm + r) * K + k0 + c4);
    }
#pragma unroll
    for (int l = 0; l < 4; l++) {
        int idx = t + l * 256;
        int r = idx >> 3, c4 = (idx & 7) * 4;
        cp16(bb + (r * GS + c4) * 4, B + (size_t)(bn + r) * K + k0 + c4);
    }
    CP_COMMIT();
}

__global__ __launch_bounds__(256, 2) void gemm_tf32_kernel(
    const float* __restrict__ A,
    const float* __restrict__ B0, const float* __restrict__ bias0,
    float* __restrict__ C0,
    const float* __restrict__ B1, const float* __restrict__ bias1,
    float* __restrict__ C1,
    int N, int K, int rnd)
{
    extern __shared__ float sm[];
    const uint32_t sb = (uint32_t)__cvta_generic_to_shared(sm);

    const float* B    = blockIdx.z ? B1 : B0;
    const float* bias = blockIdx.z ? bias1 : bias0;
    float*       C    = blockIdx.z ? C1 : C0;

    const int t    = threadIdx.x;
    const int w    = t >> 5;
    const int lane = t & 31;
    const int g    = lane >> 2;
    const int tq   = lane & 3;
    const int wm   = w & 3;
    const int wn   = w >> 2;
    const int bm   = blockIdx.y * 128;
    const int bn   = blockIdx.x * 128;

    float acc[2][8][4];
#pragma unroll
    for (int i = 0; i < 2; i++)
#pragma unroll
        for (int j = 0; j < 8; j++)
#pragma unroll
            for (int r = 0; r < 4; r++) acc[i][j][r] = 0.f;

    g_load(sb, 0, A, B, bm, bn, K, 0, t);

    for (int k0 = 0; k0 < K; k0 += 32) {
        const int cur = (k0 >> 5) & 1;
        CP_WAIT0();
        __syncthreads();
        if (k0 + 32 < K)
            g_load(sb, cur ^ 1, A, B, bm, bn, K, k0 + 32, t);

        const float* As = sm + cur * G_STAGE;
        const float* Bs = As + 128 * GS;

#pragma unroll
        for (int ks = 0; ks < 4; ks++) {
            const int kk = ks * 8;
            uint32_t a[2][4], b[8][2];
#pragma unroll
            for (int i = 0; i < 2; i++) {
                const float* ar = As + (wm * 32 + i * 16 + g) * GS + kk + tq;
                a[i][0] = __float_as_uint(ar[0]);
                a[i][1] = __float_as_uint(ar[8 * GS]);
                a[i][2] = __float_as_uint(ar[4]);
                a[i][3] = __float_as_uint(ar[8 * GS + 4]);
            }
#pragma unroll
            for (int j = 0; j < 8; j++) {
                const float* br = Bs + (wn * 64 + j * 8 + g) * GS + kk + tq;
                b[j][0] = __float_as_uint(br[0]);
                b[j][1] = __float_as_uint(br[4]);
            }
#pragma unroll
            for (int i = 0; i < 2; i++)
#pragma unroll
                for (int j = 0; j < 8; j++)
                    mma_tf32(acc[i][j], a[i][0], a[i][1], a[i][2], a[i][3],
                             b[j][0], b[j][1]);
        }
    }

#pragma unroll
    for (int i = 0; i < 2; i++) {
        int row0 = bm + wm * 32 + i * 16 + g;
#pragma unroll
        for (int j = 0; j < 8; j++) {
            int col0 = bn + wn * 64 + j * 8 + 2 * tq;
            float b0 = bias[col0], b1 = bias[col0 + 1];
            float v00 = acc[i][j][0] + b0, v01 = acc[i][j][1] + b1;
            float v10 = acc[i][j][2] + b0, v11 = acc[i][j][3] + b1;
            if (rnd) { v00 = tf32r(v00); v01 = tf32r(v01);
                       v10 = tf32r(v10); v11 = tf32r(v11); }
            *(float2*)(C + (size_t)row0 * N + col0)       = make_float2(v00, v01);
            *(float2*)(C + (size_t)(row0 + 8) * N + col0) = make_float2(v10, v11);
        }
    }
}

// ---------------------------------------------------------------------------
// Fused attention: 128-query tile, 4 warps x 32 rows (2 m16 tiles/warp),
// every K/V B-fragment reused by 2 MMAs. Single-buffered K/V, 2 CTAs/SM.
// scores = (2 q_i.k_j - |q_i|^2 - |k_j|^2)*0.125 <= ~0 -> softmax w/o max.
// ---------------------------------------------------------------------------
#define SWS 68
#define VSd 72
#define OFF_K  0
#define OFF_V  8704
#define OFF_S  (8704 + 9216)
#define OFF_SQ (OFF_S + 8704)
#define ATT_FL (OFF_SQ + 1024)      // 27648 floats = 110592 B

__global__ __launch_bounds__(128, 2) void attn_tf32_kernel(
    const float* __restrict__ q, const float* __restrict__ v,
    const float* __restrict__ sqg, float* __restrict__ o)
{
    extern __shared__ float sm[];
    const uint32_t sb = (uint32_t)__cvta_generic_to_shared(sm);

    const int bh = blockIdx.y;
    const int b  = bh >> 4;
    const int h  = bh & 15;
    const int qt = blockIdx.x * 128;
    const int t    = threadIdx.x;
    const int w    = t >> 5;
    const int lane = t & 31;
    const int g    = lane >> 2;
    const int tq   = lane & 3;
    const int i0   = 32 * w;           // warp owns rows [i0, i0+32)

    const float* qbase = q + (size_t)b * 1024 * DIM + h * 64;
    const float* vbase = v + (size_t)b * 1024 * DIM + h * 64;

    // prefetch K/V tile 0 (128 rows x 64 floats each; 16 float4/thread each)
#pragma unroll
    for (int l = 0; l < 16; l++) {
        int idx = t + l * 128;
        int r = idx >> 4, c4 = (idx & 15) * 4;
        cp16(sb + (OFF_K + r * SWS + c4) * 4, qbase + (size_t)r * DIM + c4);
        cp16(sb + (OFF_V + r * VSd + c4) * 4, vbase + (size_t)r * DIM + c4);
    }
    CP_COMMIT();

    // |q|^2 table for this (b,h): 1024 floats = 256 float4
    ((float4*)(sm + OFF_SQ))[t]       = ((const float4*)(sqg + (size_t)bh * 1024))[t];
    ((float4*)(sm + OFF_SQ))[t + 128] = ((const float4*)(sqg + (size_t)bh * 1024))[t + 128];

    // stage Q tile into S region (transient)
    float* Qs = sm + OFF_S;
#pragma unroll
    for (int l = 0; l < 16; l++) {
        int idx = t + l * 128;
        int r = idx >> 4, c4 = (idx & 15) * 4;
        *(float4*)(Qs + r * SWS + c4) =
            *(const float4*)(qbase + (size_t)(qt + r) * DIM + c4);
    }
    __syncthreads();

    // hoist Q fragments: 2 m16 tiles x 8 k-steps
    uint32_t qa[2][8][4];
#pragma unroll
    for (int m = 0; m < 2; m++)
#pragma unroll
        for (int ks = 0; ks < 8; ks++) {
            const float* qr = Qs + (i0 + m * 16 + g) * SWS + ks * 8 + tq;
            qa[m][ks][0] = __float_as_uint(qr[0]);
            qa[m][ks][1] = __float_as_uint(qr[8 * SWS]);
            qa[m][ks][2] = __float_as_uint(qr[4]);
            qa[m][ks][3] = __float_as_uint(qr[8 * SWS + 4]);
        }
    const float* sqa = sm + OFF_SQ;
    float si[2][2];
#pragma unroll
    for (int m = 0; m < 2; m++) {
        si[m][0] = sqa[qt + i0 + m * 16 + g];
        si[m][1] = sqa[qt + i0 + m * 16 + 8 + g];
    }

    CP_WAIT0();
    __syncthreads();   // K0/V0 ready; Q staging consumed -> S reusable

    float oacc[2][8][4];
#pragma unroll
    for (int m = 0; m < 2; m++)
#pragma unroll
        for (int j = 0; j < 8; j++)
#pragma unroll
            for (int r = 0; r < 4; r++) oacc[m][j][r] = 0.f;
    float den[2][2] = {{0.f, 0.f}, {0.f, 0.f}};
    const float scale = 0.125f;
    float* Swb = sm + OFF_S + w * (32 * SWS);   // 32 rows per warp
    const float* Ksc = sm + OFF_K;
    const float* Vsc = sm + OFF_V;

    for (int kt = 0; kt < 1024; kt += 128) {
        const float* sqk = sqa + kt;

#pragma unroll
        for (int jc = 0; jc < 4; jc++) {
            const int par = (jc & 1) * 32;
            float c[2][4][4];
#pragma unroll
            for (int m = 0; m < 2; m++)
#pragma unroll
                for (int jj = 0; jj < 4; jj++)
#pragma unroll
                    for (int r = 0; r < 4; r++) c[m][jj][r] = 0.f;

            // scores: B-fragment loaded once, used by both m-tiles
#pragma unroll
            for (int ks = 0; ks < 8; ks++) {
#pragma unroll
                for (int jj = 0; jj < 4; jj++) {
                    const float* kr = Ksc + ((jc * 4 + jj) * 8 + g) * SWS + ks * 8 + tq;
                    uint32_t b0 = __float_as_uint(kr[0]);
                    uint32_t b1 = __float_as_uint(kr[4]);
                    mma_tf32(c[0][jj], qa[0][ks][0], qa[0][ks][1],
                             qa[0][ks][2], qa[0][ks][3], b0, b1);
                    mma_tf32(c[1][jj], qa[1][ks][0], qa[1][ks][1],
                             qa[1][ks][2], qa[1][ks][3], b0, b1);
                }
            }
            // exp + round + store + denom
#pragma unroll
            for (int m = 0; m < 2; m++) {
#pragma unroll
                for (int jj = 0; jj < 4; jj++) {
                    int cb = jj * 8 + 2 * tq;
                    float sj0 = sqk[jc * 32 + cb], sj1 = sqk[jc * 32 + cb + 1];
                    float e00 = tf32r(__expf((2.f * c[m][jj][0] - si[m][0] - sj0) * scale));
                    float e01 = tf32r(__expf((2.f * c[m][jj][1] - si[m][0] - sj1) * scale));
                    float e10 = tf32r(__expf((2.f * c[m][jj][2] - si[m][1] - sj0) * scale));
                    float e11 = tf32r(__expf((2.f * c[m][jj][3] - si[m][1] - sj1) * scale));
                    den[m][0] += e00 + e01;
                    den[m][1] += e10 + e11;
                    *(float2*)(Swb + (m * 16 + g) * SWS + par + cb)     = make_float2(e00, e01);
                    *(float2*)(Swb + (m * 16 + 8 + g) * SWS + par + cb) = make_float2(e10, e11);
                }
            }
            __syncwarp();
            // PV: V B-fragment loaded once, used by both m-tiles
#pragma unroll
            for (int ksl = 0; ksl < 4; ksl++) {
                uint32_t a[2][4];
#pragma unroll
                for (int m = 0; m < 2; m++) {
                    const float* sr = Swb + (m * 16 + g) * SWS + par + ksl * 8 + tq;
                    a[m][0] = __float_as_uint(sr[0]);
                    a[m][1] = __float_as_uint(sr[8 * SWS]);
                    a[m][2] = __float_as_uint(sr[4]);
                    a[m][3] = __float_as_uint(sr[8 * SWS + 4]);
                }
                const int vrow = jc * 32 + ksl * 8 + tq;
#pragma unroll
                for (int j = 0; j < 8; j++) {
                    uint32_t b0 = __float_as_uint(Vsc[vrow * VSd + j * 8 + g]);
                    uint32_t b1 = __float_as_uint(Vsc[(vrow + 4) * VSd + j * 8 + g]);
                    mma_tf32(oacc[0][j], a[0][0], a[0][1], a[0][2], a[0][3], b0, b1);
                    mma_tf32(oacc[1][j], a[1][0], a[1][1], a[1][2], a[1][3], b0, b1);
                }
            }
        }
        __syncthreads();   // all warps done with K/V buffers

        if (kt + 128 < 1024) {
#pragma unroll
            for (int l = 0; l < 16; l++) {
                int idx = t + l * 128;
                int r = idx >> 4, c4 = (idx & 15) * 4;
                cp16(sb + (OFF_K + r * SWS + c4) * 4,
                     qbase + (size_t)(kt + 128 + r) * DIM + c4);
                cp16(sb + (OFF_V + r * VSd + c4) * 4,
                     vbase + (size_t)(kt + 128 + r) * DIM + c4);
            }
            CP_COMMIT();
            CP_WAIT0();
            __syncthreads();
        }
    }

    // quad-reduce denominators, normalize, write O
#pragma unroll
    for (int m = 0; m < 2; m++) {
        den[m][0] += __shfl_xor_sync(0xffffffffu, den[m][0], 1);
        den[m][0] += __shfl_xor_sync(0xffffffffu, den[m][0], 2);
        den[m][1] += __shfl_xor_sync(0xffffffffu, den[m][1], 1);
        den[m][1] += __shfl_xor_sync(0xffffffffu, den[m][1], 2);
        const float inv_lo = 1.f / den[m][0];
        const float inv_hi = 1.f / den[m][1];
        float* orow_lo = o + (size_t)(b * 1024 + qt + i0 + m * 16 + g) * DIM + h * 64;
        float* orow_hi = o + (size_t)(b * 1024 + qt + i0 + m * 16 + 8 + g) * DIM + h * 64;
#pragma unroll
        for (int j = 0; j < 8; j++) {
            int col = j * 8 + 2 * tq;
            *(float2*)(orow_lo + col) = make_float2(tf32r(oacc[m][j][0] * inv_lo),
                                                    tf32r(oacc[m][j][1] * inv_lo));
            *(float2*)(orow_hi + col) = make_float2(tf32r(oacc[m][j][2] * inv_hi),
                                                    tf32r(oacc[m][j][3] * inv_hi));
        }
    }
}

// ---------------------------------------------------------------------------
extern "C" void kernel_launch(void* const* d_in, const int* in_sizes, int n_in,
                              void* d_out, int out_size)
{
    const float* x  = (const float*)d_in[0];
    const float* Wq = (const float*)d_in[1];
    const float* bq = (const float*)d_in[2];
    const float* Wv = (const float*)d_in[3];
    const float* bv = (const float*)d_in[4];
    const float* Wo = (const float*)d_in[5];
    const float* bo = (const float*)d_in[6];
    float* out = (float*)d_out;

    float *qp, *vp, *ap, *xp, *wqp, *wvp, *wop, *sqp;
    cudaGetSymbolAddress((void**)&qp,  g_q);
    cudaGetSymbolAddress((void**)&vp,  g_v);
    cudaGetSymbolAddress((void**)&ap,  g_a);
    cudaGetSymbolAddress((void**)&xp,  g_x);
    cudaGetSymbolAddress((void**)&wqp, g_wq);
    cudaGetSymbolAddress((void**)&wvp, g_wv);
    cudaGetSymbolAddress((void**)&wop, g_wo);
    cudaGetSymbolAddress((void**)&sqp, g_sq);

    cudaFuncSetAttribute(gemm_tf32_kernel,
                         cudaFuncAttributeMaxDynamicSharedMemorySize, GEMM_SMEM);
    cudaFuncSetAttribute(attn_tf32_kernel,
                         cudaFuncAttributeMaxDynamicSharedMemorySize,
                         (int)(ATT_FL * sizeof(float)));

    round_all_kernel<<<4096, 256>>>(
        (const float4*)x,  (float4*)xp,
        (const float4*)Wq, (float4*)wqp,
        (const float4*)Wv, (float4*)wvp,
        (const float4*)Wo, (float4*)wop);

    gemm_tf32_kernel<<<dim3(8, 32, 2), 256, GEMM_SMEM>>>(
        xp, wqp, bq, qp, wvp, bv, vp, DIM, DIM, 1);

    sq_kernel<<<256, 256>>>(qp, sqp);

    attn_tf32_kernel<<<dim3(8, 64), 128, ATT_FL * sizeof(float)>>>(qp, vp, sqp, ap);

    gemm_tf32_kernel<<<dim3(8, 32, 1), 256, GEMM_SMEM>>>(
        ap, wop, bo, out, wop, bo, out, DIM, DIM, 0);
}

// round 7
// speedup vs baseline: 5.0584x; 1.0119x over previous
#include <cuda_runtime.h>
#include <cstdint>

// ---------------------------------------------------------------------------
// L2Attention via tf32 mma.sync (m16n8k8).
// Attention: intra-warp pipelining (scores of chunk jc+1 issued between
// softmax(jc) and PV(jc)) keeps the tensor pipe fed during MUFU bursts.
// b=4, n=1024, dim=1024, heads=16, d=64
// ---------------------------------------------------------------------------

#define M_ROWS 4096
#define DIM    1024

__device__ float g_q[M_ROWS * DIM];
__device__ float g_v[M_ROWS * DIM];
__device__ float g_a[M_ROWS * DIM];
__device__ float g_x[M_ROWS * DIM];
__device__ float g_wq[DIM * DIM];
__device__ float g_wv[DIM * DIM];
__device__ float g_wo[DIM * DIM];
__device__ float g_sq[64 * 1024];     // |q|^2 * 0.125 * log2(e) per (b,h,n)

#define C2EXP 0.36067376022224085f    // 2 * 0.125 * log2(e)

__device__ __forceinline__ float tf32r(float x) {
    uint32_t u;
    asm("cvt.rna.tf32.f32 %0, %1;" : "=r"(u) : "f"(x));
    return __uint_as_float(u);
}
__device__ __forceinline__ float ex2(float x) {
    float r;
    asm("ex2.approx.f32 %0, %1;" : "=f"(r) : "f"(x));
    return r;
}

__device__ __forceinline__ void mma_tf32(float c[4],
                                         uint32_t a0, uint32_t a1,
                                         uint32_t a2, uint32_t a3,
                                         uint32_t b0, uint32_t b1) {
    asm volatile(
        "mma.sync.aligned.m16n8k8.row.col.f32.tf32.tf32.f32 "
        "{%0,%1,%2,%3}, {%4,%5,%6,%7}, {%8,%9}, {%0,%1,%2,%3};\n"
        : "+f"(c[0]), "+f"(c[1]), "+f"(c[2]), "+f"(c[3])
        : "r"(a0), "r"(a1), "r"(a2), "r"(a3), "r"(b0), "r"(b1));
}

__device__ __forceinline__ void cp16(uint32_t smem_u32, const float* gptr) {
    asm volatile("cp.async.cg.shared.global [%0], [%1], 16;\n"
                 :: "r"(smem_u32), "l"(gptr));
}
#define CP_COMMIT() asm volatile("cp.async.commit_group;\n" ::: "memory")
#define CP_WAIT0()  asm volatile("cp.async.wait_group 0;\n" ::: "memory")

// ---------------------------------------------------------------------------
// one launch: round x + Wq + Wv + Wo to tf32 (RNA)
// ---------------------------------------------------------------------------
__global__ __launch_bounds__(256) void round_all_kernel(
    const float4* __restrict__ x,  float4* __restrict__ xo,
    const float4* __restrict__ w0, float4* __restrict__ w0o,
    const float4* __restrict__ w1, float4* __restrict__ w1o,
    const float4* __restrict__ w2, float4* __restrict__ w2o)
{
    int i = blockIdx.x * 256 + threadIdx.x;
    {
        float4 v = x[i];
        v.x = tf32r(v.x); v.y = tf32r(v.y);
        v.z = tf32r(v.z); v.w = tf32r(v.w);
        xo[i] = v;
    }
    if (i < 262144) {
        float4 a = w0[i], b = w1[i], c = w2[i];
        a.x = tf32r(a.x); a.y = tf32r(a.y); a.z = tf32r(a.z); a.w = tf32r(a.w);
        b.x = tf32r(b.x); b.y = tf32r(b.y); b.z = tf32r(b.z); b.w = tf32r(b.w);
        c.x = tf32r(c.x); c.y = tf32r(c.y); c.z = tf32r(c.z); c.w = tf32r(c.w);
        w0o[i] = a; w1o[i] = b; w2o[i] = c;
    }
}

// ---------------------------------------------------------------------------
// scaled |q|^2 table: sqg[(b*16+h)*1024+n] = |q_bhn|^2 * 0.125 * log2(e)
// ---------------------------------------------------------------------------
__global__ __launch_bounds__(256) void sq_kernel(
    const float* __restrict__ q, float* __restrict__ sqg)
{
    int o  = blockIdx.x * 256 + threadIdx.x;
    int n  = o & 1023;
    int bh = o >> 10;
    int b  = bh >> 4, h = bh & 15;
    const float4* p = (const float4*)(q + ((size_t)(b * 1024 + n)) * DIM + h * 64);
    float s = 0.f;
#pragma unroll
    for (int i = 0; i < 16; i++) {
        float4 v = p[i];
        s += v.x * v.x + v.y * v.y + v.z * v.z + v.w * v.w;
    }
    sqg[o] = s * (0.5f * C2EXP);
}

// ---------------------------------------------------------------------------
// GEMM (unchanged): 256 thr, 8 warps (4M x 2N), tile 128x128, K-step 32,
// 2-stage cp.async. blockIdx.z selects output -> fused Q/V projection.
// ---------------------------------------------------------------------------
#define GS 36
#define G_STAGE (2 * 128 * GS)
#define GEMM_SMEM (2 * G_STAGE * 4)

__device__ __forceinline__ void g_load(
    uint32_t sb, int st, const float* __restrict__ A,
    const float* __restrict__ B, int bm, int bn, int K, int k0, int t)
{
    uint32_t ab = sb + st * G_STAGE * 4;
    uint32_t bb = ab + 128 * GS * 4;
#pragma unroll
    for (int l = 0; l < 4; l++) {
        int idx = t + l * 256;
        int r = idx >> 3, c4 = (idx & 7) * 4;
        cp16(ab + (r * GS + c4) * 4, A + (size_t)(bm + r) * K + k0 + c4);
    }
#pragma unroll
    for (int l = 0; l < 4; l++) {
        int idx = t + l * 256;
        int r = idx >> 3, c4 = (idx & 7) * 4;
        cp16(bb + (r * GS + c4) * 4, B + (size_t)(bn + r) * K + k0 + c4);
    }
    CP_COMMIT();
}

__global__ __launch_bounds__(256, 2) void gemm_tf32_kernel(
    const float* __restrict__ A,
    const float* __restrict__ B0, const float* __restrict__ bias0,
    float* __restrict__ C0,
    const float* __restrict__ B1, const float* __restrict__ bias1,
    float* __restrict__ C1,
    int N, int K, int rnd)
{
    extern __shared__ float sm[];
    const uint32_t sb = (uint32_t)__cvta_generic_to_shared(sm);

    const float* B    = blockIdx.z ? B1 : B0;
    const float* bias = blockIdx.z ? bias1 : bias0;
    float*       C    = blockIdx.z ? C1 : C0;

    const int t    = threadIdx.x;
    const int w    = t >> 5;
    const int lane = t & 31;
    const int g    = lane >> 2;
    const int tq   = lane & 3;
    const int wm   = w & 3;
    const int wn   = w >> 2;
    const int bm   = blockIdx.y * 128;
    const int bn   = blockIdx.x * 128;

    float acc[2][8][4];
#pragma unroll
    for (int i = 0; i < 2; i++)
#pragma unroll
        for (int j = 0; j < 8; j++)
#pragma unroll
            for (int r = 0; r < 4; r++) acc[i][j][r] = 0.f;

    g_load(sb, 0, A, B, bm, bn, K, 0, t);

    for (int k0 = 0; k0 < K; k0 += 32) {
        const int cur = (k0 >> 5) & 1;
        CP_WAIT0();
        __syncthreads();
        if (k0 + 32 < K)
            g_load(sb, cur ^ 1, A, B, bm, bn, K, k0 + 32, t);

        const float* As = sm + cur * G_STAGE;
        const float* Bs = As + 128 * GS;

#pragma unroll
        for (int ks = 0; ks < 4; ks++) {
            const int kk = ks * 8;
            uint32_t a[2][4], b[8][2];
#pragma unroll
            for (int i = 0; i < 2; i++) {
                const float* ar = As + (wm * 32 + i * 16 + g) * GS + kk + tq;
                a[i][0] = __float_as_uint(ar[0]);
                a[i][1] = __float_as_uint(ar[8 * GS]);
                a[i][2] = __float_as_uint(ar[4]);
                a[i][3] = __float_as_uint(ar[8 * GS + 4]);
            }
#pragma unroll
            for (int j = 0; j < 8; j++) {
                const float* br = Bs + (wn * 64 + j * 8 + g) * GS + kk + tq;
                b[j][0] = __float_as_uint(br[0]);
                b[j][1] = __float_as_uint(br[4]);
            }
#pragma unroll
            for (int i = 0; i < 2; i++)
#pragma unroll
                for (int j = 0; j < 8; j++)
                    mma_tf32(acc[i][j], a[i][0], a[i][1], a[i][2], a[i][3],
                             b[j][0], b[j][1]);
        }
    }

#pragma unroll
    for (int i = 0; i < 2; i++) {
        int row0 = bm + wm * 32 + i * 16 + g;
#pragma unroll
        for (int j = 0; j < 8; j++) {
            int col0 = bn + wn * 64 + j * 8 + 2 * tq;
            float b0 = bias[col0], b1 = bias[col0 + 1];
            float v00 = acc[i][j][0] + b0, v01 = acc[i][j][1] + b1;
            float v10 = acc[i][j][2] + b0, v11 = acc[i][j][3] + b1;
            if (rnd) { v00 = tf32r(v00); v01 = tf32r(v01);
                       v10 = tf32r(v10); v11 = tf32r(v11); }
            *(float2*)(C + (size_t)row0 * N + col0)       = make_float2(v00, v01);
            *(float2*)(C + (size_t)(row0 + 8) * N + col0) = make_float2(v10, v11);
        }
    }
}

// ---------------------------------------------------------------------------
// Fused attention: 128-query tile, 8 warps x 16 rows, single-buffered K/V,
// 2 CTAs/SM. Pipelined chunks: softmax(jc) -> scores(jc+1) -> PV(jc).
// p = exp2(qk*C2 - si' - sj')  with si', sj' = |q|^2*0.125*log2e (table).
// ---------------------------------------------------------------------------
#define SWS 68
#define VSd 72
#define OFF_K  0
#define OFF_V  8704
#define OFF_S  (8704 + 9216)
#define OFF_SQ (OFF_S + 8704)
#define ATT_FL (OFF_SQ + 1024)      // 27648 floats = 110592 B

__global__ __launch_bounds__(256, 2) void attn_tf32_kernel(
    const float* __restrict__ q, const float* __restrict__ v,
    const float* __restrict__ sqg, float* __restrict__ o)
{
    extern __shared__ float sm[];
    const uint32_t sb = (uint32_t)__cvta_generic_to_shared(sm);

    const int bh = blockIdx.y;
    const int b  = bh >> 4;
    const int h  = bh & 15;
    const int qt = blockIdx.x * 128;
    const int t    = threadIdx.x;
    const int w    = t >> 5;
    const int lane = t & 31;
    const int g    = lane >> 2;
    const int tq   = lane & 3;
    const int i0   = 16 * w;

    const float* qbase = q + (size_t)b * 1024 * DIM + h * 64;
    const float* vbase = v + (size_t)b * 1024 * DIM + h * 64;

    // prefetch K/V tile 0
#pragma unroll
    for (int l = 0; l < 8; l++) {
        int idx = t + l * 256;
        int r = idx >> 4, c4 = (idx & 15) * 4;
        cp16(sb + (OFF_K + r * SWS + c4) * 4, qbase + (size_t)r * DIM + c4);
        cp16(sb + (OFF_V + r * VSd + c4) * 4, vbase + (size_t)r * DIM + c4);
    }
    CP_COMMIT();

    // scaled |q|^2 table for this (b,h)
    ((float4*)(sm + OFF_SQ))[t] = ((const float4*)(sqg + (size_t)bh * 1024))[t];

    // stage Q tile into S region (transient)
    float* Qs = sm + OFF_S;
#pragma unroll
    for (int l = 0; l < 8; l++) {
        int idx = t + l * 256;
        int r = idx >> 4, c4 = (idx & 15) * 4;
        *(float4*)(Qs + r * SWS + c4) =
            *(const float4*)(qbase + (size_t)(qt + r) * DIM + c4);
    }
    __syncthreads();

    uint32_t qa[8][4];
#pragma unroll
    for (int ks = 0; ks < 8; ks++) {
        const float* qr = Qs + (i0 + g) * SWS + ks * 8 + tq;
        qa[ks][0] = __float_as_uint(qr[0]);
        qa[ks][1] = __float_as_uint(qr[8 * SWS]);
        qa[ks][2] = __float_as_uint(qr[4]);
        qa[ks][3] = __float_as_uint(qr[8 * SWS + 4]);
    }
    const float* sqa = sm + OFF_SQ;
    const float si_lo = sqa[qt + i0 + g];
    const float si_hi = sqa[qt + i0 + 8 + g];

    CP_WAIT0();
    __syncthreads();   // K0/V0 ready; Q staging consumed -> S reusable

    float oacc[8][4];
#pragma unroll
    for (int j = 0; j < 8; j++)
#pragma unroll
        for (int r = 0; r < 4; r++) oacc[j][r] = 0.f;
    float den_lo = 0.f, den_hi = 0.f;
    float* Swb = sm + OFF_S + w * (16 * SWS);
    const float* Ksc = sm + OFF_K;
    const float* Vsc = sm + OFF_V;

    for (int kt = 0; kt < 1024; kt += 128) {
        const float* sqk = sqa + kt;

        float c[4][4];
        // ---- scores chunk 0 ----
#pragma unroll
        for (int jj = 0; jj < 4; jj++)
#pragma unroll
            for (int r = 0; r < 4; r++) c[jj][r] = 0.f;
#pragma unroll
        for (int ks = 0; ks < 8; ks++)
#pragma unroll
            for (int jj = 0; jj < 4; jj++) {
                const float* kr = Ksc + (jj * 8 + g) * SWS + ks * 8 + tq;
                mma_tf32(c[jj], qa[ks][0], qa[ks][1], qa[ks][2], qa[ks][3],
                         __float_as_uint(kr[0]), __float_as_uint(kr[4]));
            }

#pragma unroll
        for (int jc = 0; jc < 4; jc++) {
            const int par = (jc & 1) * 32;

            // ---- softmax(jc): consume c -> S chunk + denom ----
#pragma unroll
            for (int jj = 0; jj < 4; jj++) {
                int cb = jj * 8 + 2 * tq;
                float sj0 = sqk[jc * 32 + cb], sj1 = sqk[jc * 32 + cb + 1];
                float n_l0 = -si_lo - sj0, n_l1 = -si_lo - sj1;
                float n_h0 = -si_hi - sj0, n_h1 = -si_hi - sj1;
                float e00 = tf32r(ex2(fmaf(c[jj][0], C2EXP, n_l0)));
                float e01 = tf32r(ex2(fmaf(c[jj][1], C2EXP, n_l1)));
                float e10 = tf32r(ex2(fmaf(c[jj][2], C2EXP, n_h0)));
                float e11 = tf32r(ex2(fmaf(c[jj][3], C2EXP, n_h1)));
                den_lo += e00 + e01;
                den_hi += e10 + e11;
                *(float2*)(Swb + g * SWS + par + cb)       = make_float2(e00, e01);
                *(float2*)(Swb + (g + 8) * SWS + par + cb) = make_float2(e10, e11);
            }
            __syncwarp();

            // ---- scores(jc+1): refill c (tensor pipe stays fed) ----
            if (jc < 3) {
#pragma unroll
                for (int jj = 0; jj < 4; jj++)
#pragma unroll
                    for (int r = 0; r < 4; r++) c[jj][r] = 0.f;
#pragma unroll
                for (int ks = 0; ks < 8; ks++)
#pragma unroll
                    for (int jj = 0; jj < 4; jj++) {
                        const float* kr = Ksc + (((jc + 1) * 4 + jj) * 8 + g) * SWS + ks * 8 + tq;
                        mma_tf32(c[jj], qa[ks][0], qa[ks][1], qa[ks][2], qa[ks][3],
                                 __float_as_uint(kr[0]), __float_as_uint(kr[4]));
                    }
            }

            // ---- PV(jc) ----
#pragma unroll
            for (int ksl = 0; ksl < 4; ksl++) {
                const float* sr = Swb + g * SWS + par + ksl * 8 + tq;
                uint32_t a0 = __float_as_uint(sr[0]);
                uint32_t a1 = __float_as_uint(sr[8 * SWS]);
                uint32_t a2 = __float_as_uint(sr[4]);
                uint32_t a3 = __float_as_uint(sr[8 * SWS + 4]);
                const int vrow = jc * 32 + ksl * 8 + tq;
#pragma unroll
                for (int j = 0; j < 8; j++) {
                    uint32_t b0 = __float_as_uint(Vsc[vrow * VSd + j * 8 + g]);
                    uint32_t b1 = __float_as_uint(Vsc[(vrow + 4) * VSd + j * 8 + g]);
                    mma_tf32(oacc[j], a0, a1, a2, a3, b0, b1);
                }
            }
        }
        __syncthreads();   // all warps done with K/V buffers

        if (kt + 128 < 1024) {
#pragma unroll
            for (int l = 0; l < 8; l++) {
                int idx = t + l * 256;
                int r = idx >> 4, c4 = (idx & 15) * 4;
                cp16(sb + (OFF_K + r * SWS + c4) * 4,
                     qbase + (size_t)(kt + 128 + r) * DIM + c4);
                cp16(sb + (OFF_V + r * VSd + c4) * 4,
                     vbase + (size_t)(kt + 128 + r) * DIM + c4);
            }
            CP_COMMIT();
            CP_WAIT0();
            __syncthreads();
        }
    }

    den_lo += __shfl_xor_sync(0xffffffffu, den_lo, 1);
    den_lo += __shfl_xor_sync(0xffffffffu, den_lo, 2);
    den_hi += __shfl_xor_sync(0xffffffffu, den_hi, 1);
    den_hi += __shfl_xor_sync(0xffffffffu, den_hi, 2);
    const float inv_lo = 1.f / den_lo;
    const float inv_hi = 1.f / den_hi;

    float* orow_lo = o + (size_t)(b * 1024 + qt + i0 + g) * DIM + h * 64;
    float* orow_hi = o + (size_t)(b * 1024 + qt + i0 + 8 + g) * DIM + h * 64;
#pragma unroll
    for (int j = 0; j < 8; j++) {
        int col = j * 8 + 2 * tq;
        *(float2*)(orow_lo + col) = make_float2(tf32r(oacc[j][0] * inv_lo),
                                                tf32r(oacc[j][1] * inv_lo));
        *(float2*)(orow_hi + col) = make_float2(tf32r(oacc[j][2] * inv_hi),
                                                tf32r(oacc[j][3] * inv_hi));
    }
}

// ---------------------------------------------------------------------------
extern "C" void kernel_launch(void* const* d_in, const int* in_sizes, int n_in,
                              void* d_out, int out_size)
{
    const float* x  = (const float*)d_in[0];
    const float* Wq = (const float*)d_in[1];
    const float* bq = (const float*)d_in[2];
    const float* Wv = (const float*)d_in[3];
    const float* bv = (const float*)d_in[4];
    const float* Wo = (const float*)d_in[5];
    const float* bo = (const float*)d_in[6];
    float* out = (float*)d_out;

    float *qp, *vp, *ap, *xp, *wqp, *wvp, *wop, *sqp;
    cudaGetSymbolAddress((void**)&qp,  g_q);
    cudaGetSymbolAddress((void**)&vp,  g_v);
    cudaGetSymbolAddress((void**)&ap,  g_a);
    cudaGetSymbolAddress((void**)&xp,  g_x);
    cudaGetSymbolAddress((void**)&wqp, g_wq);
    cudaGetSymbolAddress((void**)&wvp, g_wv);
    cudaGetSymbolAddress((void**)&wop, g_wo);
    cudaGetSymbolAddress((void**)&sqp, g_sq);

    cudaFuncSetAttribute(gemm_tf32_kernel,
                         cudaFuncAttributeMaxDynamicSharedMemorySize, GEMM_SMEM);
    cudaFuncSetAttribute(attn_tf32_kernel,
                         cudaFuncAttributeMaxDynamicSharedMemorySize,
                         (int)(ATT_FL * sizeof(float)));

    round_all_kernel<<<4096, 256>>>(
        (const float4*)x,  (float4*)xp,
        (const float4*)Wq, (float4*)wqp,
        (const float4*)Wv, (float4*)wvp,
        (const float4*)Wo, (float4*)wop);

    gemm_tf32_kernel<<<dim3(8, 32, 2), 256, GEMM_SMEM>>>(
        xp, wqp, bq, qp, wvp, bv, vp, DIM, DIM, 1);

    sq_kernel<<<256, 256>>>(qp, sqp);

    attn_tf32_kernel<<<dim3(8, 64), 256, ATT_FL * sizeof(float)>>>(qp, vp, sqp, ap);

    gemm_tf32_kernel<<<dim3(8, 32, 1), 256, GEMM_SMEM>>>(
        ap, wop, bo, out, wop, bo, out, DIM, DIM, 0);
}

// round 8
// speedup vs baseline: 5.1118x; 1.0106x over previous
#include <cuda_runtime.h>
#include <cstdint>

// ---------------------------------------------------------------------------
// L2Attention via tf32 mma.sync (m16n8k8).
// Attention: 2-stage 64-key ring pipeline (loads overlap compute),
// softmax pipelined between score and PV MMAs.
// b=4, n=1024, dim=1024, heads=16, d=64
// ---------------------------------------------------------------------------

#define M_ROWS 4096
#define DIM    1024

__device__ float g_q[M_ROWS * DIM];
__device__ float g_v[M_ROWS * DIM];
__device__ float g_a[M_ROWS * DIM];
__device__ float g_x[M_ROWS * DIM];
__device__ float g_wq[DIM * DIM];
__device__ float g_wv[DIM * DIM];
__device__ float g_wo[DIM * DIM];
__device__ float g_sq[64 * 1024];     // |q|^2 * 0.125 * log2(e) per (b,h,n)

#define C2EXP 0.36067376022224085f    // 2 * 0.125 * log2(e)

__device__ __forceinline__ float tf32r(float x) {
    uint32_t u;
    asm("cvt.rna.tf32.f32 %0, %1;" : "=r"(u) : "f"(x));
    return __uint_as_float(u);
}
__device__ __forceinline__ float ex2(float x) {
    float r;
    asm("ex2.approx.f32 %0, %1;" : "=f"(r) : "f"(x));
    return r;
}

__device__ __forceinline__ void mma_tf32(float c[4],
                                         uint32_t a0, uint32_t a1,
                                         uint32_t a2, uint32_t a3,
                                         uint32_t b0, uint32_t b1) {
    asm volatile(
        "mma.sync.aligned.m16n8k8.row.col.f32.tf32.tf32.f32 "
        "{%0,%1,%2,%3}, {%4,%5,%6,%7}, {%8,%9}, {%0,%1,%2,%3};\n"
        : "+f"(c[0]), "+f"(c[1]), "+f"(c[2]), "+f"(c[3])
        : "r"(a0), "r"(a1), "r"(a2), "r"(a3), "r"(b0), "r"(b1));
}

__device__ __forceinline__ void cp16(uint32_t smem_u32, const float* gptr) {
    asm volatile("cp.async.cg.shared.global [%0], [%1], 16;\n"
                 :: "r"(smem_u32), "l"(gptr));
}
#define CP_COMMIT() asm volatile("cp.async.commit_group;\n" ::: "memory")

// ---------------------------------------------------------------------------
// one launch: round x + Wq + Wv + Wo to tf32 (RNA)
// ---------------------------------------------------------------------------
__global__ __launch_bounds__(256) void round_all_kernel(
    const float4* __restrict__ x,  float4* __restrict__ xo,
    const float4* __restrict__ w0, float4* __restrict__ w0o,
    const float4* __restrict__ w1, float4* __restrict__ w1o,
    const float4* __restrict__ w2, float4* __restrict__ w2o)
{
    int i = blockIdx.x * 256 + threadIdx.x;
    {
        float4 v = x[i];
        v.x = tf32r(v.x); v.y = tf32r(v.y);
        v.z = tf32r(v.z); v.w = tf32r(v.w);
        xo[i] = v;
    }
    if (i < 262144) {
        float4 a = w0[i], b = w1[i], c = w2[i];
        a.x = tf32r(a.x); a.y = tf32r(a.y); a.z = tf32r(a.z); a.w = tf32r(a.w);
        b.x = tf32r(b.x); b.y = tf32r(b.y); b.z = tf32r(b.z); b.w = tf32r(b.w);
        c.x = tf32r(c.x); c.y = tf32r(c.y); c.z = tf32r(c.z); c.w = tf32r(c.w);
        w0o[i] = a; w1o[i] = b; w2o[i] = c;
    }
}

// ---------------------------------------------------------------------------
// scaled |q|^2 table: sqg[(b*16+h)*1024+n] = |q_bhn|^2 * 0.125 * log2(e)
// ---------------------------------------------------------------------------
__global__ __launch_bounds__(256) void sq_kernel(
    const float* __restrict__ q, float* __restrict__ sqg)
{
    int o  = blockIdx.x * 256 + threadIdx.x;
    int n  = o & 1023;
    int bh = o >> 10;
    int b  = bh >> 4, h = bh & 15;
    const float4* p = (const float4*)(q + ((size_t)(b * 1024 + n)) * DIM + h * 64);
    float s = 0.f;
#pragma unroll
    for (int i = 0; i < 16; i++) {
        float4 v = p[i];
        s += v.x * v.x + v.y * v.y + v.z * v.z + v.w * v.w;
    }
    sqg[o] = s * (0.5f * C2EXP);
}

// ---------------------------------------------------------------------------
// GEMM (unchanged): 256 thr, 8 warps (4M x 2N), tile 128x128, K-step 32,
// 2-stage cp.async. blockIdx.z selects output -> fused Q/V projection.
// ---------------------------------------------------------------------------
#define GS 36
#define G_STAGE (2 * 128 * GS)
#define GEMM_SMEM (2 * G_STAGE * 4)

__device__ __forceinline__ void g_load(
    uint32_t sb, int st, const float* __restrict__ A,
    const float* __restrict__ B, int bm, int bn, int K, int k0, int t)
{
    uint32_t ab = sb + st * G_STAGE * 4;
    uint32_t bb = ab + 128 * GS * 4;
#pragma unroll
    for (int l = 0; l < 4; l++) {
        int idx = t + l * 256;
        int r = idx >> 3, c4 = (idx & 7) * 4;
        cp16(ab + (r * GS + c4) * 4, A + (size_t)(bm + r) * K + k0 + c4);
    }
#pragma unroll
    for (int l = 0; l < 4; l++) {
        int idx = t + l * 256;
        int r = idx >> 3, c4 = (idx & 7) * 4;
        cp16(bb + (r * GS + c4) * 4, B + (size_t)(bn + r) * K + k0 + c4);
    }
    CP_COMMIT();
}

__global__ __launch_bounds__(256, 2) void gemm_tf32_kernel(
    const float* __restrict__ A,
    const float* __restrict__ B0, const float* __restrict__ bias0,
    float* __restrict__ C0,
    const float* __restrict__ B1, const float* __restrict__ bias1,
    float* __restrict__ C1,
    int N, int K, int rnd)
{
    extern __shared__ float sm[];
    const uint32_t sb = (uint32_t)__cvta_generic_to_shared(sm);

    const float* B    = blockIdx.z ? B1 : B0;
    const float* bias = blockIdx.z ? bias1 : bias0;
    float*       C    = blockIdx.z ? C1 : C0;

    const int t    = threadIdx.x;
    const int w    = t >> 5;
    const int lane = t & 31;
    const int g    = lane >> 2;
    const int tq   = lane & 3;
    const int wm   = w & 3;
    const int wn   = w >> 2;
    const int bm   = blockIdx.y * 128;
    const int bn   = blockIdx.x * 128;

    float acc[2][8][4];
#pragma unroll
    for (int i = 0; i < 2; i++)
#pragma unroll
        for (int j = 0; j < 8; j++)
#pragma unroll
            for (int r = 0; r < 4; r++) acc[i][j][r] = 0.f;

    g_load(sb, 0, A, B, bm, bn, K, 0, t);

    for (int k0 = 0; k0 < K; k0 += 32) {
        const int cur = (k0 >> 5) & 1;
        asm volatile("cp.async.wait_group 0;\n" ::: "memory");
        __syncthreads();
        if (k0 + 32 < K)
            g_load(sb, cur ^ 1, A, B, bm, bn, K, k0 + 32, t);

        const float* As = sm + cur * G_STAGE;
        const float* Bs = As + 128 * GS;

#pragma unroll
        for (int ks = 0; ks < 4; ks++) {
            const int kk = ks * 8;
            uint32_t a[2][4], b[8][2];
#pragma unroll
            for (int i = 0; i < 2; i++) {
                const float* ar = As + (wm * 32 + i * 16 + g) * GS + kk + tq;
                a[i][0] = __float_as_uint(ar[0]);
                a[i][1] = __float_as_uint(ar[8 * GS]);
                a[i][2] = __float_as_uint(ar[4]);
                a[i][3] = __float_as_uint(ar[8 * GS + 4]);
            }
#pragma unroll
            for (int j = 0; j < 8; j++) {
                const float* br = Bs + (wn * 64 + j * 8 + g) * GS + kk + tq;
                b[j][0] = __float_as_uint(br[0]);
                b[j][1] = __float_as_uint(br[4]);
            }
#pragma unroll
            for (int i = 0; i < 2; i++)
#pragma unroll
                for (int j = 0; j < 8; j++)
                    mma_tf32(acc[i][j], a[i][0], a[i][1], a[i][2], a[i][3],
                             b[j][0], b[j][1]);
        }
    }

#pragma unroll
    for (int i = 0; i < 2; i++) {
        int row0 = bm + wm * 32 + i * 16 + g;
#pragma unroll
        for (int j = 0; j < 8; j++) {
            int col0 = bn + wn * 64 + j * 8 + 2 * tq;
            float b0 = bias[col0], b1 = bias[col0 + 1];
            float v00 = acc[i][j][0] + b0, v01 = acc[i][j][1] + b1;
            float v10 = acc[i][j][2] + b0, v11 = acc[i][j][3] + b1;
            if (rnd) { v00 = tf32r(v00); v01 = tf32r(v01);
                       v10 = tf32r(v10); v11 = tf32r(v11); }
            *(float2*)(C + (size_t)row0 * N + col0)       = make_float2(v00, v01);
            *(float2*)(C + (size_t)(row0 + 8) * N + col0) = make_float2(v10, v11);
        }
    }
}

// ---------------------------------------------------------------------------
// Fused attention: 128-query tile, 8 warps x 16 rows, 2 CTAs/SM.
// K/V streamed as 16 tiles of 64 keys through a 2-stage cp.async ring:
// tile i+2's load issues after tile i's buffers free, completes during
// tile i+1's compute -> global latency fully hidden.
// p = exp2(qk*C2 - si' - sj');   scores <= ~0 -> softmax w/o running max.
// ---------------------------------------------------------------------------
#define SWS 68
#define VSd 72
#define KST (64 * SWS)              // 4352 floats per K stage
#define VST (64 * VSd)              // 4608 floats per V stage
#define OFF_K  0                    // 2 stages: 8704
#define OFF_V  (2 * KST)            // 2 stages: 9216
#define OFF_S  (OFF_V + 2 * VST)    // 8704 (S chunks; Q staging in prologue)
#define OFF_SQ (OFF_S + 8704)       // 1024
#define ATT_FL (OFF_SQ + 1024)      // 27648 floats = 110592 B

// stage one 64-key tile (K + V) into ring stage s
__device__ __forceinline__ void a_load(
    uint32_t sb, int s, const float* __restrict__ qb,
    const float* __restrict__ vb, int key0, int t)
{
#pragma unroll
    for (int l = 0; l < 4; l++) {
        int idx = t + l * 256;                // 0..1023
        int r = idx >> 4, c4 = (idx & 15) * 4;
        cp16(sb + (OFF_K + s * KST + r * SWS + c4) * 4,
             qb + (size_t)(key0 + r) * DIM + c4);
        cp16(sb + (OFF_V + s * VST + r * VSd + c4) * 4,
             vb + (size_t)(key0 + r) * DIM + c4);
    }
    CP_COMMIT();
}

__global__ __launch_bounds__(256, 2) void attn_tf32_kernel(
    const float* __restrict__ q, const float* __restrict__ v,
    const float* __restrict__ sqg, float* __restrict__ o)
{
    extern __shared__ float sm[];
    const uint32_t sb = (uint32_t)__cvta_generic_to_shared(sm);

    const int bh = blockIdx.y;
    const int b  = bh >> 4;
    const int h  = bh & 15;
    const int qt = blockIdx.x * 128;
    const int t    = threadIdx.x;
    const int w    = t >> 5;
    const int lane = t & 31;
    const int g    = lane >> 2;
    const int tq   = lane & 3;
    const int i0   = 16 * w;

    const float* qbase = q + (size_t)b * 1024 * DIM + h * 64;
    const float* vbase = v + (size_t)b * 1024 * DIM + h * 64;

    // prefetch tiles 0 and 1 into the ring
    a_load(sb, 0, qbase, vbase, 0, t);
    a_load(sb, 1, qbase, vbase, 64, t);

    // scaled |q|^2 table for this (b,h)
    ((float4*)(sm + OFF_SQ))[t] = ((const float4*)(sqg + (size_t)bh * 1024))[t];

    // stage Q tile into S region (transient)
    float* Qs = sm + OFF_S;
#pragma unroll
    for (int l = 0; l < 8; l++) {
        int idx = t + l * 256;
        int r = idx >> 4, c4 = (idx & 15) * 4;
        *(float4*)(Qs + r * SWS + c4) =
            *(const float4*)(qbase + (size_t)(qt + r) * DIM + c4);
    }
    __syncthreads();

    uint32_t qa[8][4];
#pragma unroll
    for (int ks = 0; ks < 8; ks++) {
        const float* qr = Qs + (i0 + g) * SWS + ks * 8 + tq;
        qa[ks][0] = __float_as_uint(qr[0]);
        qa[ks][1] = __float_as_uint(qr[8 * SWS]);
        qa[ks][2] = __float_as_uint(qr[4]);
        qa[ks][3] = __float_as_uint(qr[8 * SWS + 4]);
    }
    const float* sqa = sm + OFF_SQ;
    const float si_lo = sqa[qt + i0 + g];
    const float si_hi = sqa[qt + i0 + 8 + g];
    __syncthreads();   // Q staging fully consumed -> S region reusable

    float oacc[8][4];
#pragma unroll
    for (int j = 0; j < 8; j++)
#pragma unroll
        for (int r = 0; r < 4; r++) oacc[j][r] = 0.f;
    float den_lo = 0.f, den_hi = 0.f;
    float* Swb = sm + OFF_S + w * (16 * SWS);

    for (int it = 0; it < 16; it++) {
        const int s = it & 1;
        // tile it's loads complete (tile it+1's group may stay in flight)
        if (it < 15)
            asm volatile("cp.async.wait_group 1;\n" ::: "memory");
        else
            asm volatile("cp.async.wait_group 0;\n" ::: "memory");
        __syncthreads();

        const float* Ksc = sm + OFF_K + s * KST;
        const float* Vsc = sm + OFF_V + s * VST;
        const float* sqk = sqa + it * 64;

        float c[4][4];
        // ---- scores chunk 0 (keys 0..31 of tile) ----
#pragma unroll
        for (int jj = 0; jj < 4; jj++)
#pragma unroll
            for (int r = 0; r < 4; r++) c[jj][r] = 0.f;
#pragma unroll
        for (int ks = 0; ks < 8; ks++)
#pragma unroll
            for (int jj = 0; jj < 4; jj++) {
                const float* kr = Ksc + (jj * 8 + g) * SWS + ks * 8 + tq;
                mma_tf32(c[jj], qa[ks][0], qa[ks][1], qa[ks][2], qa[ks][3],
                         __float_as_uint(kr[0]), __float_as_uint(kr[4]));
            }

#pragma unroll
        for (int jc = 0; jc < 2; jc++) {
            const int par = jc * 32;

            // ---- softmax(jc) ----
#pragma unroll
            for (int jj = 0; jj < 4; jj++) {
                int cb = jj * 8 + 2 * tq;
                float sj0 = sqk[par + cb], sj1 = sqk[par + cb + 1];
                float e00 = tf32r(ex2(fmaf(c[jj][0], C2EXP, -si_lo - sj0)));
                float e01 = tf32r(ex2(fmaf(c[jj][1], C2EXP, -si_lo - sj1)));
                float e10 = tf32r(ex2(fmaf(c[jj][2], C2EXP, -si_hi - sj0)));
                float e11 = tf32r(ex2(fmaf(c[jj][3], C2EXP, -si_hi - sj1)));
                den_lo += e00 + e01;
                den_hi += e10 + e11;
                *(float2*)(Swb + g * SWS + par + cb)       = make_float2(e00, e01);
                *(float2*)(Swb + (g + 8) * SWS + par + cb) = make_float2(e10, e11);
            }
            __syncwarp();

            // ---- scores(jc+1): refill c while tensor pipe drains ----
            if (jc < 1) {
#pragma unroll
                for (int jj = 0; jj < 4; jj++)
#pragma unroll
                    for (int r = 0; r < 4; r++) c[jj][r] = 0.f;
#pragma unroll
                for (int ks = 0; ks < 8; ks++)
#pragma unroll
                    for (int jj = 0; jj < 4; jj++) {
                        const float* kr = Ksc + ((4 + jj) * 8 + g) * SWS + ks * 8 + tq;
                        mma_tf32(c[jj], qa[ks][0], qa[ks][1], qa[ks][2], qa[ks][3],
                                 __float_as_uint(kr[0]), __float_as_uint(kr[4]));
                    }
            }

            // ---- PV(jc) ----
#pragma unroll
            for (int ksl = 0; ksl < 4; ksl++) {
                const float* sr = Swb + g * SWS + par + ksl * 8 + tq;
                uint32_t a0 = __float_as_uint(sr[0]);
                uint32_t a1 = __float_as_uint(sr[8 * SWS]);
                uint32_t a2 = __float_as_uint(sr[4]);
                uint32_t a3 = __float_as_uint(sr[8 * SWS + 4]);
                const int vrow = par + ksl * 8 + tq;
#pragma unroll
                for (int j = 0; j < 8; j++) {
                    uint32_t b0 = __float_as_uint(Vsc[vrow * VSd + j * 8 + g]);
                    uint32_t b1 = __float_as_uint(Vsc[(vrow + 4) * VSd + j * 8 + g]);
                    mma_tf32(oacc[j], a0, a1, a2, a3, b0, b1);
                }
            }
        }
        __syncthreads();   // stage s fully consumed by all warps

        // refill stage s with tile it+2 (completes during tile it+1 compute)
        if (it + 2 < 16)
            a_load(sb, s, qbase, vbase, (it + 2) * 64, t);
    }

    den_lo += __shfl_xor_sync(0xffffffffu, den_lo, 1);
    den_lo += __shfl_xor_sync(0xffffffffu, den_lo, 2);
    den_hi += __shfl_xor_sync(0xffffffffu, den_hi, 1);
    den_hi += __shfl_xor_sync(0xffffffffu, den_hi, 2);
    const float inv_lo = 1.f / den_lo;
    const float inv_hi = 1.f / den_hi;

    float* orow_lo = o + (size_t)(b * 1024 + qt + i0 + g) * DIM + h * 64;
    float* orow_hi = o + (size_t)(b * 1024 + qt + i0 + 8 + g) * DIM + h * 64;
#pragma unroll
    for (int j = 0; j < 8; j++) {
        int col = j * 8 + 2 * tq;
        *(float2*)(orow_lo + col) = make_float2(tf32r(oacc[j][0] * inv_lo),
                                                tf32r(oacc[j][1] * inv_lo));
        *(float2*)(orow_hi + col) = make_float2(tf32r(oacc[j][2] * inv_hi),
                                                tf32r(oacc[j][3] * inv_hi));
    }
}

// ---------------------------------------------------------------------------
extern "C" void kernel_launch(void* const* d_in, const int* in_sizes, int n_in,
                              void* d_out, int out_size)
{
    const float* x  = (const float*)d_in[0];
    const float* Wq = (const float*)d_in[1];
    const float* bq = (const float*)d_in[2];
    const float* Wv = (const float*)d_in[3];
    const float* bv = (const float*)d_in[4];
    const float* Wo = (const float*)d_in[5];
    const float* bo = (const float*)d_in[6];
    float* out = (float*)d_out;

    float *qp, *vp, *ap, *xp, *wqp, *wvp, *wop, *sqp;
    cudaGetSymbolAddress((void**)&qp,  g_q);
    cudaGetSymbolAddress((void**)&vp,  g_v);
    cudaGetSymbolAddress((void**)&ap,  g_a);
    cudaGetSymbolAddress((void**)&xp,  g_x);
    cudaGetSymbolAddress((void**)&wqp, g_wq);
    cudaGetSymbolAddress((void**)&wvp, g_wv);
    cudaGetSymbolAddress((void**)&wop, g_wo);
    cudaGetSymbolAddress((void**)&sqp, g_sq);

    cudaFuncSetAttribute(gemm_tf32_kernel,
                         cudaFuncAttributeMaxDynamicSharedMemorySize, GEMM_SMEM);
    cudaFuncSetAttribute(attn_tf32_kernel,
                         cudaFuncAttributeMaxDynamicSharedMemorySize,
                         (int)(ATT_FL * sizeof(float)));

    round_all_kernel<<<4096, 256>>>(
        (const float4*)x,  (float4*)xp,
        (const float4*)Wq, (float4*)wqp,
        (const float4*)Wv, (float4*)wvp,
        (const float4*)Wo, (float4*)wop);

    gemm_tf32_kernel<<<dim3(8, 32, 2), 256, GEMM_SMEM>>>(
        xp, wqp, bq, qp, wvp, bv, vp, DIM, DIM, 1);

    sq_kernel<<<256, 256>>>(qp, sqp);

    attn_tf32_kernel<<<dim3(8, 64), 256, ATT_FL * sizeof(float)>>>(qp, vp, sqp, ap);

    gemm_tf32_kernel<<<dim3(8, 32, 1), 256, GEMM_SMEM>>>(
        ap, wop, bo, out, wop, bo, out, DIM, DIM, 0);
}